// round 9
// baseline (speedup 1.0000x reference)
#include <cuda_runtime.h>
#include <cstdint>

#define N_C 50000
#define N_V 100000
#define N_A 5000
#define E_C2V 1600000
#define E_A2V 1000000
#define NSCAN_BLK ((N_V + 1023)/1024)

// ---------------- static device scratch ----------------
__device__ __align__(16) float g_P_gv_v[N_V*32];
__device__ __align__(16) float g_P_hv_v[N_V*32];
__device__ __align__(16) float g_P_fv_v[N_V*32];
__device__ __align__(16) float g_P_ga_v[N_V*32];
__device__ __align__(16) float g_P_gv_c[N_C*32];
__device__ __align__(16) float g_P_hv_a[N_A*32];
__device__ __align__(16) float g_P_ga_a[N_A*32];
__device__ __align__(16) float g_P_fa_a[N_A*32];
__device__ __align__(16) float g_acc_gv[N_V*32];   // MEAN (written by nodeagg)
__device__ __align__(16) float g_acc_hv[N_V*32];   // SUM (atomic path)
__device__ __align__(16) float g_acc_ga[N_A*32];   // SUM (atomic path)
__device__ float g_cnt_gv[N_V];                    // unused this round (kept for k_edge)
__device__ float g_cnt_hv[N_V];
__device__ float g_cnt_ga[N_A];
// CSR (gv only)
__device__ int   g_cnti[N_V];
__device__ int   g_rs[N_V+1];
__device__ int   g_cur[N_V];
__device__ int   g_part[NSCAN_BLK+1];
__device__ int   g_pO[E_C2V];
__device__ float g_pA[E_C2V];

static __device__ __forceinline__ unsigned f2tf(float f){
  unsigned u; asm("cvt.rna.tf32.f32 %0, %1;" : "=r"(u) : "f"(f)); return u;
}
static __device__ __forceinline__ void mma8(float d[4], const unsigned a[4],
                                            unsigned b0, unsigned b1){
  asm volatile("mma.sync.aligned.m16n8k8.row.col.f32.tf32.tf32.f32 "
      "{%0,%1,%2,%3},{%4,%5,%6,%7},{%8,%9},{%0,%1,%2,%3};"
      : "+f"(d[0]),"+f"(d[1]),"+f"(d[2]),"+f"(d[3])
      : "r"(a[0]),"r"(a[1]),"r"(a[2]),"r"(a[3]),"r"(b0),"r"(b1));
}
static __device__ __forceinline__ void red4(float* p, float a, float b, float c, float d){
  asm volatile("red.global.add.v4.f32 [%0], {%1,%2,%3,%4};"
               :: "l"(p), "f"(a), "f"(b), "f"(c), "f"(d) : "memory");
}

__global__ void k_zero(){
  int i = blockIdx.x*blockDim.x + threadIdx.x;
  int stride = gridDim.x*blockDim.x;
  float4 z = make_float4(0.f,0.f,0.f,0.f);
  for (int j=i;j<N_V*8;j+=stride) ((float4*)g_acc_hv)[j]=z;
  for (int j=i;j<N_V;j+=stride) g_cnt_hv[j]=0.f;
  for (int j=i;j<N_A*8;j+=stride) ((float4*)g_acc_ga)[j]=z;
  for (int j=i;j<N_A;j+=stride) g_cnt_ga[j]=0.f;
}

// ---------------- CSR build for gv (bins = v-node target of c2v) ----------------
__global__ void k_zero_cnt(){
  int i = blockIdx.x*256 + threadIdx.x;
  if (i < N_V) g_cnti[i] = 0;
}
__global__ void k_hist(const int* __restrict__ c2v_t){
  int e = blockIdx.x*256 + threadIdx.x;
  if (e < E_C2V) atomicAdd(&g_cnti[c2v_t[e]], 1);
}
__global__ void k_s1(){
  __shared__ int s[1024];
  int t = threadIdx.x, i = blockIdx.x*1024 + t;
  s[t] = (i < N_V) ? g_cnti[i] : 0;
  __syncthreads();
  for (int off=512; off>=1; off>>=1){ if (t<off) s[t]+=s[t+off]; __syncthreads(); }
  if (t==0) g_part[blockIdx.x] = s[0];
}
__global__ void k_s2(){
  __shared__ int s[128];
  int t = threadIdx.x;
  int v = (t < NSCAN_BLK) ? g_part[t] : 0;
  s[t] = v; __syncthreads();
  for (int off=1; off<128; off<<=1){
    int y = (t>=off) ? s[t-off] : 0; __syncthreads();
    s[t] += y; __syncthreads();
  }
  if (t < NSCAN_BLK) g_part[t] = s[t] - v;
}
__global__ void k_s3(){
  __shared__ int s[1024];
  int t = threadIdx.x, i = blockIdx.x*1024 + t;
  int v = (i < N_V) ? g_cnti[i] : 0;
  s[t] = v; __syncthreads();
  for (int off=1; off<1024; off<<=1){
    int y = (t>=off) ? s[t-off] : 0; __syncthreads();
    s[t] += y; __syncthreads();
  }
  if (i < N_V){
    int start = g_part[blockIdx.x] + s[t] - v;
    g_rs[i] = start; g_cur[i] = start;
  }
  if (blockIdx.x==0 && t==0) g_rs[N_V] = E_C2V;
}
__global__ void k_scatter(const int* __restrict__ c2v_s, const int* __restrict__ c2v_t,
                          const float* __restrict__ ea_c2v){
  int e = blockIdx.x*256 + threadIdx.x;
  if (e < E_C2V){
    int p = atomicAdd(&g_cur[c2v_t[e]], 1);
    g_pO[p] = c2v_s[e]; g_pA[p] = ea_c2v[e];
  }
}

// ---------------- fused per-node projections ----------------
__global__ void __launch_bounds__(256) k_pre3(
    const float* __restrict__ x, int n_nodes, int din, int nsets,
    const float* __restrict__ Wa, const float* __restrict__ Wb,
    const float* __restrict__ Wc, int which)
{
  __shared__ float s_w[3*14*32];
  const float* Ws[3] = {Wa, Wb, Wc};
  for (int m=0;m<nsets;m++)
    for (int i=threadIdx.x;i<din*32;i+=256) s_w[m*din*32+i] = Ws[m][i];
  __syncthreads();
  int node = blockIdx.x*256 + threadIdx.x;
  if (node >= n_nodes) return;
  float xr[14];
  const float* xp = x + (size_t)node*din;
  for (int k=0;k<din;k++) xr[k]=xp[k];
  for (int m=0;m<nsets;m++){
    float* out;
    if (which == 0) out = (m==0)?g_P_gv_v:((m==1)?g_P_hv_v:g_P_fv_v);
    else if (which == 1) out = g_P_gv_c;
    else out = (m==0)?g_P_hv_a:((m==1)?g_P_ga_a:g_P_fa_a);
    const float* w = &s_w[m*din*32];
    float* op = out + (size_t)node*32;
#pragma unroll
    for (int cg=0;cg<8;cg++){
      float4 a = make_float4(0.f,0.f,0.f,0.f);
      for (int k=0;k<din;k++){
        float4 ww = *(const float4*)&w[k*32+cg*4];
        a.x += xr[k]*ww.x; a.y += xr[k]*ww.y; a.z += xr[k]*ww.z; a.w += xr[k]*ww.w;
      }
      *(float4*)&op[cg*4] = a;
    }
  }
}

// ---------------- edge-centric MLP + atomic scatter (validated; modes 1,2) ----------------
__global__ void __launch_bounds__(256) k_edge(
    int ntiles, int mode,
    const int* __restrict__ src, const int* __restrict__ tgt,
    const float* __restrict__ attr,
    const float* __restrict__ W1, int rowoff_we,
    const float* __restrict__ b1,
    const float* __restrict__ W2, const float* __restrict__ b2)
{
  const float* Ps; const float* Pt; float* acc; float* cnt;
  if (mode == 0){ Ps=g_P_gv_c; Pt=g_P_gv_v; acc=g_acc_gv; cnt=g_cnt_gv; }
  else if (mode == 1){ Ps=g_P_hv_a; Pt=g_P_hv_v; acc=g_acc_hv; cnt=g_cnt_hv; }
  else { Ps=g_P_ga_a; Pt=g_P_ga_v; acc=g_acc_ga; cnt=g_cnt_ga; }
  const int* agg = (mode == 2) ? src : tgt;

  const int lane = threadIdx.x & 31, q = lane & 3, g = lane >> 2;
  const int lowq = (q & 1) == 0;
  const int colh = 4*(q >> 1);

  unsigned bf[4][4][2];
#pragma unroll
  for (int k=0;k<4;k++)
#pragma unroll
    for (int n=0;n<4;n++){
      bf[k][n][0] = f2tf(W2[(8*k+q)*32 + 8*n + g]);
      bf[k][n][1] = f2tf(W2[(8*k+q+4)*32 + 8*n + g]);
    }
  float we[8], bb1[8];
#pragma unroll
  for (int k=0;k<4;k++){
    we[2*k]   = W1[rowoff_we*32 + 8*k+q];
    we[2*k+1] = W1[rowoff_we*32 + 8*k+q+4];
    bb1[2*k]  = b1[8*k+q];
    bb1[2*k+1]= b1[8*k+q+4];
  }
  float b2g[2][4];
#pragma unroll
  for (int j=0;j<2;j++){
    int n = lowq ? j : 2+j;
#pragma unroll
    for (int i=0;i<4;i++) b2g[j][i] = b2[8*n + colh + i];
  }

  int warp = blockIdx.x*8 + (threadIdx.x>>5);
  int nw = gridDim.x*8;
  for (int tile = warp; tile < ntiles; tile += nw){
    int e0 = tile*16 + g, e1 = e0 + 8;
    int s0 = src[e0], t0 = tgt[e0];
    int s1 = src[e1], t1 = tgt[e1];
    float at0 = attr[e0], at1 = attr[e1];
    const float* ps0 = Ps + (size_t)s0*32; const float* pt0 = Pt + (size_t)t0*32;
    const float* ps1 = Ps + (size_t)s1*32; const float* pt1 = Pt + (size_t)t1*32;
    unsigned af[4][4];
#pragma unroll
    for (int k=0;k<4;k++){
      int c0 = 8*k+q, c1 = c0+4;
      af[k][0] = f2tf(fmaxf(pt0[c0]+ps0[c0]+at0*we[2*k]+bb1[2*k], 0.f));
      af[k][1] = f2tf(fmaxf(pt1[c0]+ps1[c0]+at1*we[2*k]+bb1[2*k], 0.f));
      af[k][2] = f2tf(fmaxf(pt0[c1]+ps0[c1]+at0*we[2*k+1]+bb1[2*k+1], 0.f));
      af[k][3] = f2tf(fmaxf(pt1[c1]+ps1[c1]+at1*we[2*k+1]+bb1[2*k+1], 0.f));
    }
    float d[4][4];
#pragma unroll
    for (int n=0;n<4;n++){
      d[n][0]=0.f; d[n][1]=0.f; d[n][2]=0.f; d[n][3]=0.f;
#pragma unroll
      for (int k=0;k<4;k++) mma8(d[n], af[k], bf[k][n][0], bf[k][n][1]);
    }
    float sh[4][4];
#pragma unroll
    for (int n=0;n<4;n++)
#pragma unroll
      for (int j=0;j<4;j++) sh[n][j] = __shfl_xor_sync(0xffffffffu, d[n][j], 1);

    int i0 = (mode==2)?s0:t0, i1 = (mode==2)?s1:t1;
    float* a0 = acc + (size_t)i0*32;
    float* a1 = acc + (size_t)i1*32;
#pragma unroll
    for (int j=0;j<2;j++){
      int n = lowq ? j : 2+j;
      int c = 8*n + colh;
      float v0,v1,v2,v3, w0,w1,w2,w3;
      if (lowq){ v0=d[n][0]; v1=d[n][1]; v2=sh[n][0]; v3=sh[n][1];
                 w0=d[n][2]; w1=d[n][3]; w2=sh[n][2]; w3=sh[n][3]; }
      else     { v0=sh[n][0]; v1=sh[n][1]; v2=d[n][0]; v3=d[n][1];
                 w0=sh[n][2]; w1=sh[n][3]; w2=d[n][2]; w3=d[n][3]; }
      red4(a0 + c, fmaxf(v0+b2g[j][0],0.f), fmaxf(v1+b2g[j][1],0.f),
                   fmaxf(v2+b2g[j][2],0.f), fmaxf(v3+b2g[j][3],0.f));
      red4(a1 + c, fmaxf(w0+b2g[j][0],0.f), fmaxf(w1+b2g[j][1],0.f),
                   fmaxf(w2+b2g[j][2],0.f), fmaxf(w3+b2g[j][3],0.f));
    }
    if (lane < 16) atomicAdd(cnt + agg[tile*16+lane], 1.0f);
  }
}

// ---------------- node-centric CSR aggregation (gv only this round) ----------------
__global__ void __launch_bounds__(256) k_nodeagg(
    int n_nodes,
    const float* __restrict__ Pown, const float* __restrict__ Poth,
    const float* __restrict__ W1, int rowoff_we,
    const float* __restrict__ b1,
    const float* __restrict__ W2, const float* __restrict__ b2,
    float* __restrict__ outacc)
{
  int warp = blockIdx.x*8 + (threadIdx.x>>5);
  if (warp >= n_nodes) return;
  const int lane = threadIdx.x & 31, q = lane & 3, g = lane >> 2;

  unsigned bf[4][4][2];
#pragma unroll
  for (int k=0;k<4;k++)
#pragma unroll
    for (int n=0;n<4;n++){
      bf[k][n][0] = f2tf(W2[(8*k+q)*32 + 8*n + g]);
      bf[k][n][1] = f2tf(W2[(8*k+q+4)*32 + 8*n + g]);
    }
  float we[8], bb1[8];
#pragma unroll
  for (int k=0;k<4;k++){
    we[2*k]   = W1[rowoff_we*32 + 8*k+q];
    we[2*k+1] = W1[rowoff_we*32 + 8*k+q+4];
    bb1[2*k]  = b1[8*k+q];
    bb1[2*k+1]= b1[8*k+q+4];
  }
  float b2r[4][2];
#pragma unroll
  for (int n=0;n<4;n++){ b2r[n][0] = b2[8*n+2*q]; b2r[n][1] = b2[8*n+2*q+1]; }

  int node = warp;
  int rs = g_rs[node], re = g_rs[node+1];
  int deg = re - rs;
  const float* po = Pown + (size_t)node*32;
  float own[8];
#pragma unroll
  for (int k=0;k<4;k++){ own[2*k] = po[8*k+q]; own[2*k+1] = po[8*k+q+4]; }

  float sacc[4][4];
#pragma unroll
  for (int n=0;n<4;n++){ sacc[n][0]=0.f; sacc[n][1]=0.f; sacc[n][2]=0.f; sacc[n][3]=0.f; }

  for (int base = rs; base < re; base += 16){
    int e0 = base + g, e1 = base + 8 + g;
    bool v0 = e0 < re, v1 = e1 < re;
    int o0 = g_pO[v0 ? e0 : rs];
    int o1 = g_pO[v1 ? e1 : rs];
    float at0 = v0 ? g_pA[e0] : 0.f;
    float at1 = v1 ? g_pA[e1] : 0.f;
    const float* p0 = Poth + (size_t)o0*32;
    const float* p1 = Poth + (size_t)o1*32;
    unsigned af[4][4];
#pragma unroll
    for (int k=0;k<4;k++){
      int c0 = 8*k+q, c1 = c0+4;
      af[k][0] = f2tf(fmaxf(own[2*k]   + p0[c0] + at0*we[2*k]   + bb1[2*k],   0.f));
      af[k][1] = f2tf(fmaxf(own[2*k]   + p1[c0] + at1*we[2*k]   + bb1[2*k],   0.f));
      af[k][2] = f2tf(fmaxf(own[2*k+1] + p0[c1] + at0*we[2*k+1] + bb1[2*k+1], 0.f));
      af[k][3] = f2tf(fmaxf(own[2*k+1] + p1[c1] + at1*we[2*k+1] + bb1[2*k+1], 0.f));
    }
#pragma unroll
    for (int n=0;n<4;n++){
      float d[4] = {0.f,0.f,0.f,0.f};
#pragma unroll
      for (int k=0;k<4;k++) mma8(d, af[k], bf[k][n][0], bf[k][n][1]);
      if (v0){ sacc[n][0] += fmaxf(d[0]+b2r[n][0],0.f); sacc[n][1] += fmaxf(d[1]+b2r[n][1],0.f); }
      if (v1){ sacc[n][2] += fmaxf(d[2]+b2r[n][0],0.f); sacc[n][3] += fmaxf(d[3]+b2r[n][1],0.f); }
    }
  }
  float inv = 1.f / (float)max(deg, 1);
  float* op2 = outacc + (size_t)node*32;
#pragma unroll
  for (int n=0;n<4;n++){
    float s0 = sacc[n][0] + sacc[n][2];
    float s1 = sacc[n][1] + sacc[n][3];
    s0 += __shfl_xor_sync(0xffffffffu, s0, 4);
    s0 += __shfl_xor_sync(0xffffffffu, s0, 8);
    s0 += __shfl_xor_sync(0xffffffffu, s0, 16);
    s1 += __shfl_xor_sync(0xffffffffu, s1, 4);
    s1 += __shfl_xor_sync(0xffffffffu, s1, 8);
    s1 += __shfl_xor_sync(0xffffffffu, s1, 16);
    if (g == 0) *(float2*)&op2[8*n+2*q] = make_float2(s0*inv, s1*inv);
  }
}

// ---------------- f_v node MLP: gv part is MEAN, hv part is SUM/cnt ----------------
__global__ void __launch_bounds__(256) k_fv(
    const float* __restrict__ fvW1, const float* __restrict__ fvb1,
    const float* __restrict__ fvW2, const float* __restrict__ fvb2,
    const float* __restrict__ gaW1)
{
  __shared__ __align__(16) float s_W1[64*32];
  __shared__ __align__(16) float s_W2[32*32];
  __shared__ __align__(16) float s_Wg[32*32];
  __shared__ float s_b1[32], s_b2[32];
  for (int i=threadIdx.x;i<64*32;i+=256) s_W1[i]=fvW1[13*32+i];
  for (int i=threadIdx.x;i<32*32;i+=256){ s_W2[i]=fvW2[i]; s_Wg[i]=gaW1[14*32+i]; }
  if (threadIdx.x<32){ s_b1[threadIdx.x]=fvb1[threadIdx.x]; s_b2[threadIdx.x]=fvb2[threadIdx.x]; }
  __syncthreads();
  int n = blockIdx.x*256 + threadIdx.x;
  if (n >= N_V) return;
  float ih = 1.f/fmaxf(g_cnt_hv[n],1.f);
  float h[32];
#pragma unroll
  for (int c=0;c<32;c++) h[c] = g_P_fv_v[(size_t)n*32+c] + s_b1[c];
#pragma unroll 4
  for (int k=0;k<32;k++){
    float g = g_acc_gv[(size_t)n*32+k];          // already the mean
#pragma unroll
    for (int cg=0;cg<8;cg++){
      float4 w = *(const float4*)&s_W1[k*32+cg*4];
      h[cg*4+0]+=g*w.x; h[cg*4+1]+=g*w.y; h[cg*4+2]+=g*w.z; h[cg*4+3]+=g*w.w;
    }
  }
#pragma unroll 4
  for (int k=0;k<32;k++){
    float g = g_acc_hv[(size_t)n*32+k]*ih;
#pragma unroll
    for (int cg=0;cg<8;cg++){
      float4 w = *(const float4*)&s_W1[(32+k)*32+cg*4];
      h[cg*4+0]+=g*w.x; h[cg*4+1]+=g*w.y; h[cg*4+2]+=g*w.z; h[cg*4+3]+=g*w.w;
    }
  }
#pragma unroll
  for (int c=0;c<32;c++) h[c]=fmaxf(h[c],0.f);
  float v[32];
#pragma unroll
  for (int c=0;c<32;c++) v[c]=s_b2[c];
#pragma unroll 4
  for (int k=0;k<32;k++){
    float g = h[k];
#pragma unroll
    for (int cg=0;cg<8;cg++){
      float4 w = *(const float4*)&s_W2[k*32+cg*4];
      v[cg*4+0]+=g*w.x; v[cg*4+1]+=g*w.y; v[cg*4+2]+=g*w.z; v[cg*4+3]+=g*w.w;
    }
  }
#pragma unroll
  for (int c=0;c<32;c++) v[c]=fmaxf(v[c],0.f);
  float o[32];
#pragma unroll
  for (int c=0;c<32;c++) o[c]=0.f;
#pragma unroll 4
  for (int k=0;k<32;k++){
    float g = v[k];
#pragma unroll
    for (int cg=0;cg<8;cg++){
      float4 w = *(const float4*)&s_Wg[k*32+cg*4];
      o[cg*4+0]+=g*w.x; o[cg*4+1]+=g*w.y; o[cg*4+2]+=g*w.z; o[cg*4+3]+=g*w.w;
    }
  }
#pragma unroll
  for (int cg=0;cg<8;cg++)
    *(float4*)&g_P_ga_v[(size_t)n*32+cg*4] = make_float4(o[cg*4],o[cg*4+1],o[cg*4+2],o[cg*4+3]);
}

// ---------------- f_a node MLP -> out (ga is SUM/cnt) ----------------
__global__ void __launch_bounds__(256) k_fa(
    const float* __restrict__ faW1, const float* __restrict__ fab1,
    const float* __restrict__ faW2, const float* __restrict__ fab2,
    float* __restrict__ out)
{
  __shared__ __align__(16) float s_W1[32*32];
  __shared__ __align__(16) float s_W2[32*32];
  __shared__ float s_b1[32], s_b2[32];
  for (int i=threadIdx.x;i<32*32;i+=256){ s_W1[i]=faW1[14*32+i]; s_W2[i]=faW2[i]; }
  if (threadIdx.x<32){ s_b1[threadIdx.x]=fab1[threadIdx.x]; s_b2[threadIdx.x]=fab2[threadIdx.x]; }
  __syncthreads();
  int n = blockIdx.x*256 + threadIdx.x;
  if (n >= N_A) return;
  float ig = 1.f/fmaxf(g_cnt_ga[n],1.f);
  float h[32];
#pragma unroll
  for (int c=0;c<32;c++) h[c] = g_P_fa_a[(size_t)n*32+c] + s_b1[c];
#pragma unroll 4
  for (int k=0;k<32;k++){
    float g = g_acc_ga[(size_t)n*32+k]*ig;
#pragma unroll
    for (int cg=0;cg<8;cg++){
      float4 w = *(const float4*)&s_W1[k*32+cg*4];
      h[cg*4+0]+=g*w.x; h[cg*4+1]+=g*w.y; h[cg*4+2]+=g*w.z; h[cg*4+3]+=g*w.w;
    }
  }
#pragma unroll
  for (int c=0;c<32;c++) h[c]=fmaxf(h[c],0.f);
  float v[32];
#pragma unroll
  for (int c=0;c<32;c++) v[c]=s_b2[c];
#pragma unroll 4
  for (int k=0;k<32;k++){
    float g = h[k];
#pragma unroll
    for (int cg=0;cg<8;cg++){
      float4 w = *(const float4*)&s_W2[k*32+cg*4];
      v[cg*4+0]+=g*w.x; v[cg*4+1]+=g*w.y; v[cg*4+2]+=g*w.z; v[cg*4+3]+=g*w.w;
    }
  }
#pragma unroll
  for (int cg=0;cg<8;cg++)
    *(float4*)&out[(size_t)n*32+cg*4] = make_float4(
        fmaxf(v[cg*4+0],0.f), fmaxf(v[cg*4+1],0.f),
        fmaxf(v[cg*4+2],0.f), fmaxf(v[cg*4+3],0.f));
}

extern "C" void kernel_launch(void* const* d_in, const int* in_sizes, int n_in,
                              void* d_out, int out_size)
{
  const float* x_c   = (const float*)d_in[0];
  const float* x_v   = (const float*)d_in[1];
  const float* x_a   = (const float*)d_in[2];
  const int*   c2v_s = (const int*)d_in[3];
  const int*   c2v_t = (const int*)d_in[4];
  const int*   a2v_s = (const int*)d_in[5];
  const int*   a2v_t = (const int*)d_in[6];
  const float* ea_c2v = (const float*)d_in[7];
  const float* ea_a2v = (const float*)d_in[8];
  const float* gvW1 = (const float*)d_in[9];
  const float* gvb1 = (const float*)d_in[10];
  const float* gvW2 = (const float*)d_in[11];
  const float* gvb2 = (const float*)d_in[12];
  const float* hvW1 = (const float*)d_in[13];
  const float* hvb1 = (const float*)d_in[14];
  const float* hvW2 = (const float*)d_in[15];
  const float* hvb2 = (const float*)d_in[16];
  const float* fvW1 = (const float*)d_in[17];
  const float* fvb1 = (const float*)d_in[18];
  const float* fvW2 = (const float*)d_in[19];
  const float* fvb2 = (const float*)d_in[20];
  const float* gaW1 = (const float*)d_in[21];
  const float* gab1 = (const float*)d_in[22];
  const float* gaW2 = (const float*)d_in[23];
  const float* gab2 = (const float*)d_in[24];
  const float* faW1 = (const float*)d_in[25];
  const float* fab1 = (const float*)d_in[26];
  const float* faW2 = (const float*)d_in[27];
  const float* fab2 = (const float*)d_in[28];
  float* out = (float*)d_out;

  k_zero<<<2048, 256>>>();

  // CSR build (gv only)
  k_zero_cnt<<<(N_V+255)/256, 256>>>();
  k_hist<<<(E_C2V+255)/256, 256>>>(c2v_t);
  k_s1<<<NSCAN_BLK, 1024>>>();
  k_s2<<<1, 128>>>();
  k_s3<<<NSCAN_BLK, 1024>>>();
  k_scatter<<<(E_C2V+255)/256, 256>>>(c2v_s, c2v_t, ea_c2v);

  // projections
  k_pre3<<<(N_V+255)/256, 256>>>(x_v, N_V, 13, 3, gvW1, hvW1, fvW1, 0);
  k_pre3<<<(N_C+255)/256, 256>>>(x_c, N_C, 14, 1, gvW1 + 13*32, nullptr, nullptr, 1);
  k_pre3<<<(N_A+255)/256, 256>>>(x_a, N_A, 14, 3, hvW1 + 13*32, gaW1, faW1, 2);

  // gv: node-centric CSR (bisect target)
  k_nodeagg<<<(N_V+7)/8, 256>>>(N_V, g_P_gv_v, g_P_gv_c, gvW1, 27, gvb1, gvW2, gvb2, g_acc_gv);
  // hv: validated atomic path
  k_edge<<<1024, 256>>>(E_A2V/16, 1, a2v_s, a2v_t, ea_a2v, hvW1, 27, hvb1, hvW2, hvb2);

  k_fv<<<(N_V+255)/256, 256>>>(fvW1, fvb1, fvW2, fvb2, gaW1);

  // ga: validated atomic path
  k_edge<<<1024, 256>>>(E_A2V/16, 2, a2v_s, a2v_t, ea_a2v, gaW1, 46, gab1, gaW2, gab2);

  k_fa<<<(N_A+255)/256, 256>>>(faW1, fab1, faW2, fab2, out);
}

// round 15
// speedup vs baseline: 2.4827x; 2.4827x over previous
#include <cuda_runtime.h>
#include <cstdint>

#define N_C 50000
#define N_V 100000
#define N_A 5000
#define E_C2V 1600000
#define E_A2V 1000000
#define NB_TOT (2*N_V + N_A)          // bins: gv(t) | hv(t) | ga(s)
#define E_TOT  (E_C2V + 2*E_A2V)
#define NSCAN_BLK ((NB_TOT + 1023)/1024)

// ---------------- static device scratch ----------------
__device__ __align__(16) float g_P_gv_v[N_V*32];
__device__ __align__(16) float g_P_hv_v[N_V*32];
__device__ __align__(16) float g_P_fv_v[N_V*32];
__device__ __align__(16) float g_P_ga_v[N_V*32];
__device__ __align__(16) float g_P_gv_c[N_C*32];
__device__ __align__(16) float g_P_hv_a[N_A*32];
__device__ __align__(16) float g_P_ga_a[N_A*32];
__device__ __align__(16) float g_P_fa_a[N_A*32];
__device__ __align__(16) float g_acc_gv[N_V*32];
__device__ __align__(16) float g_acc_hv[N_V*32];
__device__ __align__(16) float g_acc_ga[N_A*32];
__device__ float g_cnt_gv[N_V];
__device__ float g_cnt_hv[N_V];
__device__ float g_cnt_ga[N_A];
// permutation build
__device__ int   g_cnti[NB_TOT];
__device__ int   g_cur[NB_TOT];
__device__ int   g_part[NSCAN_BLK+1];
// permuted edge arrays (segments ordered by agg node): [c2v | a2v-by-t | a2v-by-s]
__device__ int   g_eS[E_TOT];
__device__ int   g_eT[E_TOT];
__device__ float g_eA[E_TOT];

static __device__ __forceinline__ unsigned f2tf(float f){
  unsigned u; asm("cvt.rna.tf32.f32 %0, %1;" : "=r"(u) : "f"(f)); return u;
}
static __device__ __forceinline__ void mma8(float d[4], const unsigned a[4],
                                            unsigned b0, unsigned b1){
  asm volatile("mma.sync.aligned.m16n8k8.row.col.f32.tf32.tf32.f32 "
      "{%0,%1,%2,%3},{%4,%5,%6,%7},{%8,%9},{%0,%1,%2,%3};"
      : "+f"(d[0]),"+f"(d[1]),"+f"(d[2]),"+f"(d[3])
      : "r"(a[0]),"r"(a[1]),"r"(a[2]),"r"(a[3]),"r"(b0),"r"(b1));
}
static __device__ __forceinline__ void red4(float* p, float a, float b, float c, float d){
  asm volatile("red.global.add.v4.f32 [%0], {%1,%2,%3,%4};"
               :: "l"(p), "f"(a), "f"(b), "f"(c), "f"(d) : "memory");
}

__global__ void k_zero(){
  int i = blockIdx.x*blockDim.x + threadIdx.x;
  int stride = gridDim.x*blockDim.x;
  float4 z = make_float4(0.f,0.f,0.f,0.f);
  for (int j=i;j<N_V*8;j+=stride){ ((float4*)g_acc_gv)[j]=z; ((float4*)g_acc_hv)[j]=z; }
  for (int j=i;j<N_V;j+=stride){ g_cnt_gv[j]=0.f; g_cnt_hv[j]=0.f; }
  for (int j=i;j<N_A*8;j+=stride) ((float4*)g_acc_ga)[j]=z;
  for (int j=i;j<N_A;j+=stride) g_cnt_ga[j]=0.f;
}

// ---------------- permutation build ----------------
__global__ void k_zero_cnt(){
  int i = blockIdx.x*256 + threadIdx.x;
  if (i < NB_TOT) g_cnti[i] = 0;
}
__global__ void k_hist(const int* __restrict__ c2v_t,
                       const int* __restrict__ a2v_t,
                       const int* __restrict__ a2v_s){
  int e = blockIdx.x*256 + threadIdx.x;
  if (e < E_A2V){
    atomicAdd(&g_cnti[N_V + a2v_t[e]], 1);
    atomicAdd(&g_cnti[2*N_V + a2v_s[e]], 1);
  }
  if (e < E_C2V) atomicAdd(&g_cnti[c2v_t[e]], 1);
}
__global__ void k_s1(){
  __shared__ int s[1024];
  int t = threadIdx.x, i = blockIdx.x*1024 + t;
  s[t] = (i < NB_TOT) ? g_cnti[i] : 0;
  __syncthreads();
  for (int off=512; off>=1; off>>=1){ if (t<off) s[t]+=s[t+off]; __syncthreads(); }
  if (t==0) g_part[blockIdx.x] = s[0];
}
__global__ void k_s2(){
  __shared__ int s[256];
  int t = threadIdx.x;
  int v = (t < NSCAN_BLK) ? g_part[t] : 0;
  s[t] = v; __syncthreads();
  for (int off=1; off<256; off<<=1){
    int y = (t>=off) ? s[t-off] : 0; __syncthreads();
    s[t] += y; __syncthreads();
  }
  if (t < NSCAN_BLK) g_part[t] = s[t] - v;
}
__global__ void k_s3(){
  __shared__ int s[1024];
  int t = threadIdx.x, i = blockIdx.x*1024 + t;
  int v = (i < NB_TOT) ? g_cnti[i] : 0;
  s[t] = v; __syncthreads();
  for (int off=1; off<1024; off<<=1){
    int y = (t>=off) ? s[t-off] : 0; __syncthreads();
    s[t] += y; __syncthreads();
  }
  if (i < NB_TOT) g_cur[i] = g_part[blockIdx.x] + s[t] - v;  // exclusive start
}
__global__ void k_scatter(const int* __restrict__ c2v_s, const int* __restrict__ c2v_t,
                          const int* __restrict__ a2v_s, const int* __restrict__ a2v_t,
                          const float* __restrict__ ea_c2v, const float* __restrict__ ea_a2v){
  int e = blockIdx.x*256 + threadIdx.x;
  if (e < E_A2V){
    int s = a2v_s[e], t = a2v_t[e]; float a = ea_a2v[e];
    int p = atomicAdd(&g_cur[N_V + t], 1);
    g_eS[p] = s; g_eT[p] = t; g_eA[p] = a;
    p = atomicAdd(&g_cur[2*N_V + s], 1);
    g_eS[p] = s; g_eT[p] = t; g_eA[p] = a;
  }
  if (e < E_C2V){
    int p = atomicAdd(&g_cur[c2v_t[e]], 1);
    g_eS[p] = c2v_s[e]; g_eT[p] = c2v_t[e]; g_eA[p] = ea_c2v[e];
  }
}

// ---------------- fused per-node projections ----------------
__global__ void __launch_bounds__(256) k_pre3(
    const float* __restrict__ x, int n_nodes, int din, int nsets,
    const float* __restrict__ Wa, const float* __restrict__ Wb,
    const float* __restrict__ Wc, int which)
{
  __shared__ float s_w[3*14*32];
  const float* Ws[3] = {Wa, Wb, Wc};
  for (int m=0;m<nsets;m++)
    for (int i=threadIdx.x;i<din*32;i+=256) s_w[m*din*32+i] = Ws[m][i];
  __syncthreads();
  int node = blockIdx.x*256 + threadIdx.x;
  if (node >= n_nodes) return;
  float xr[14];
  const float* xp = x + (size_t)node*din;
  for (int k=0;k<din;k++) xr[k]=xp[k];
  for (int m=0;m<nsets;m++){
    float* out;
    if (which == 0) out = (m==0)?g_P_gv_v:((m==1)?g_P_hv_v:g_P_fv_v);
    else if (which == 1) out = g_P_gv_c;
    else out = (m==0)?g_P_hv_a:((m==1)?g_P_ga_a:g_P_fa_a);
    const float* w = &s_w[m*din*32];
    float* op = out + (size_t)node*32;
#pragma unroll
    for (int cg=0;cg<8;cg++){
      float4 a = make_float4(0.f,0.f,0.f,0.f);
      for (int k=0;k<din;k++){
        float4 ww = *(const float4*)&s_w[m*din*32 + k*32+cg*4];
        a.x += xr[k]*ww.x; a.y += xr[k]*ww.y; a.z += xr[k]*ww.z; a.w += xr[k]*ww.w;
      }
      *(float4*)&op[cg*4] = a;
    }
    (void)w;
  }
}

// ---------------- edge-centric MLP + atomic scatter over PERMUTED edges ----------------
// reads g_eS/g_eT/g_eA at [eoff + e]; semantics identical to validated round-5 kernel
__global__ void __launch_bounds__(256) k_edge(
    int ntiles, int mode, int eoff,
    const float* __restrict__ W1, int rowoff_we,
    const float* __restrict__ b1,
    const float* __restrict__ W2, const float* __restrict__ b2)
{
  const float* Ps; const float* Pt; float* acc; float* cnt;
  if (mode == 0){ Ps=g_P_gv_c; Pt=g_P_gv_v; acc=g_acc_gv; cnt=g_cnt_gv; }
  else if (mode == 1){ Ps=g_P_hv_a; Pt=g_P_hv_v; acc=g_acc_hv; cnt=g_cnt_hv; }
  else { Ps=g_P_ga_a; Pt=g_P_ga_v; acc=g_acc_ga; cnt=g_cnt_ga; }

  const int lane = threadIdx.x & 31, q = lane & 3, g = lane >> 2;
  const int lowq = (q & 1) == 0;
  const int colh = 4*(q >> 1);

  unsigned bf[4][4][2];
#pragma unroll
  for (int k=0;k<4;k++)
#pragma unroll
    for (int n=0;n<4;n++){
      bf[k][n][0] = f2tf(W2[(8*k+q)*32 + 8*n + g]);
      bf[k][n][1] = f2tf(W2[(8*k+q+4)*32 + 8*n + g]);
    }
  float we[8], bb1[8];
#pragma unroll
  for (int k=0;k<4;k++){
    we[2*k]   = W1[rowoff_we*32 + 8*k+q];
    we[2*k+1] = W1[rowoff_we*32 + 8*k+q+4];
    bb1[2*k]  = b1[8*k+q];
    bb1[2*k+1]= b1[8*k+q+4];
  }
  float b2g[2][4];
#pragma unroll
  for (int j=0;j<2;j++){
    int n = lowq ? j : 2+j;
#pragma unroll
    for (int i=0;i<4;i++) b2g[j][i] = b2[8*n + colh + i];
  }

  int warp = blockIdx.x*8 + (threadIdx.x>>5);
  int nw = gridDim.x*8;
  for (int tile = warp; tile < ntiles; tile += nw){
    int e0 = eoff + tile*16 + g, e1 = e0 + 8;
    int s0 = g_eS[e0], t0 = g_eT[e0];
    int s1 = g_eS[e1], t1 = g_eT[e1];
    float at0 = g_eA[e0], at1 = g_eA[e1];
    const float* ps0 = Ps + (size_t)s0*32; const float* pt0 = Pt + (size_t)t0*32;
    const float* ps1 = Ps + (size_t)s1*32; const float* pt1 = Pt + (size_t)t1*32;
    unsigned af[4][4];
#pragma unroll
    for (int k=0;k<4;k++){
      int c0 = 8*k+q, c1 = c0+4;
      af[k][0] = f2tf(fmaxf(pt0[c0]+ps0[c0]+at0*we[2*k]+bb1[2*k], 0.f));
      af[k][1] = f2tf(fmaxf(pt1[c0]+ps1[c0]+at1*we[2*k]+bb1[2*k], 0.f));
      af[k][2] = f2tf(fmaxf(pt0[c1]+ps0[c1]+at0*we[2*k+1]+bb1[2*k+1], 0.f));
      af[k][3] = f2tf(fmaxf(pt1[c1]+ps1[c1]+at1*we[2*k+1]+bb1[2*k+1], 0.f));
    }
    float d[4][4];
#pragma unroll
    for (int n=0;n<4;n++){
      d[n][0]=0.f; d[n][1]=0.f; d[n][2]=0.f; d[n][3]=0.f;
#pragma unroll
      for (int k=0;k<4;k++) mma8(d[n], af[k], bf[k][n][0], bf[k][n][1]);
    }
    float sh[4][4];
#pragma unroll
    for (int n=0;n<4;n++)
#pragma unroll
      for (int j=0;j<4;j++) sh[n][j] = __shfl_xor_sync(0xffffffffu, d[n][j], 1);

    int i0 = (mode==2)?s0:t0, i1 = (mode==2)?s1:t1;
    float* a0 = acc + (size_t)i0*32;
    float* a1 = acc + (size_t)i1*32;
    bool same = (i0 == i1);   // frequent after sort: merge two red4 into one
#pragma unroll
    for (int j=0;j<2;j++){
      int n = lowq ? j : 2+j;
      int c = 8*n + colh;
      float v0,v1,v2,v3, w0,w1,w2,w3;
      if (lowq){ v0=d[n][0]; v1=d[n][1]; v2=sh[n][0]; v3=sh[n][1];
                 w0=d[n][2]; w1=d[n][3]; w2=sh[n][2]; w3=sh[n][3]; }
      else     { v0=sh[n][0]; v1=sh[n][1]; v2=d[n][0]; v3=d[n][1];
                 w0=sh[n][2]; w1=sh[n][3]; w2=d[n][2]; w3=d[n][3]; }
      float rv0 = fmaxf(v0+b2g[j][0],0.f), rv1 = fmaxf(v1+b2g[j][1],0.f);
      float rv2 = fmaxf(v2+b2g[j][2],0.f), rv3 = fmaxf(v3+b2g[j][3],0.f);
      float rw0 = fmaxf(w0+b2g[j][0],0.f), rw1 = fmaxf(w1+b2g[j][1],0.f);
      float rw2 = fmaxf(w2+b2g[j][2],0.f), rw3 = fmaxf(w3+b2g[j][3],0.f);
      if (same){
        red4(a0 + c, rv0+rw0, rv1+rw1, rv2+rw2, rv3+rw3);
      } else {
        red4(a0 + c, rv0, rv1, rv2, rv3);
        red4(a1 + c, rw0, rw1, rw2, rw3);
      }
    }
    if (lane < 16){
      int idx = (mode==2) ? g_eS[eoff + tile*16+lane] : g_eT[eoff + tile*16+lane];
      atomicAdd(cnt + idx, 1.0f);
    }
  }
}

// ---------------- f_v node MLP fused with g_a projection ----------------
__global__ void __launch_bounds__(256) k_fv(
    const float* __restrict__ fvW1, const float* __restrict__ fvb1,
    const float* __restrict__ fvW2, const float* __restrict__ fvb2,
    const float* __restrict__ gaW1)
{
  __shared__ __align__(16) float s_W1[64*32];
  __shared__ __align__(16) float s_W2[32*32];
  __shared__ __align__(16) float s_Wg[32*32];
  __shared__ float s_b1[32], s_b2[32];
  for (int i=threadIdx.x;i<64*32;i+=256) s_W1[i]=fvW1[13*32+i];
  for (int i=threadIdx.x;i<32*32;i+=256){ s_W2[i]=fvW2[i]; s_Wg[i]=gaW1[14*32+i]; }
  if (threadIdx.x<32){ s_b1[threadIdx.x]=fvb1[threadIdx.x]; s_b2[threadIdx.x]=fvb2[threadIdx.x]; }
  __syncthreads();
  int n = blockIdx.x*256 + threadIdx.x;
  if (n >= N_V) return;
  float ig = 1.f/fmaxf(g_cnt_gv[n],1.f);
  float ih = 1.f/fmaxf(g_cnt_hv[n],1.f);
  float h[32];
#pragma unroll
  for (int c=0;c<32;c++) h[c] = g_P_fv_v[(size_t)n*32+c] + s_b1[c];
#pragma unroll 4
  for (int k=0;k<32;k++){
    float g = g_acc_gv[(size_t)n*32+k]*ig;
#pragma unroll
    for (int cg=0;cg<8;cg++){
      float4 w = *(const float4*)&s_W1[k*32+cg*4];
      h[cg*4+0]+=g*w.x; h[cg*4+1]+=g*w.y; h[cg*4+2]+=g*w.z; h[cg*4+3]+=g*w.w;
    }
  }
#pragma unroll 4
  for (int k=0;k<32;k++){
    float g = g_acc_hv[(size_t)n*32+k]*ih;
#pragma unroll
    for (int cg=0;cg<8;cg++){
      float4 w = *(const float4*)&s_W1[(32+k)*32+cg*4];
      h[cg*4+0]+=g*w.x; h[cg*4+1]+=g*w.y; h[cg*4+2]+=g*w.z; h[cg*4+3]+=g*w.w;
    }
  }
#pragma unroll
  for (int c=0;c<32;c++) h[c]=fmaxf(h[c],0.f);
  float v[32];
#pragma unroll
  for (int c=0;c<32;c++) v[c]=s_b2[c];
#pragma unroll 4
  for (int k=0;k<32;k++){
    float g = h[k];
#pragma unroll
    for (int cg=0;cg<8;cg++){
      float4 w = *(const float4*)&s_W2[k*32+cg*4];
      v[cg*4+0]+=g*w.x; v[cg*4+1]+=g*w.y; v[cg*4+2]+=g*w.z; v[cg*4+3]+=g*w.w;
    }
  }
#pragma unroll
  for (int c=0;c<32;c++) v[c]=fmaxf(v[c],0.f);
  float o[32];
#pragma unroll
  for (int c=0;c<32;c++) o[c]=0.f;
#pragma unroll 4
  for (int k=0;k<32;k++){
    float g = v[k];
#pragma unroll
    for (int cg=0;cg<8;cg++){
      float4 w = *(const float4*)&s_Wg[k*32+cg*4];
      o[cg*4+0]+=g*w.x; o[cg*4+1]+=g*w.y; o[cg*4+2]+=g*w.z; o[cg*4+3]+=g*w.w;
    }
  }
#pragma unroll
  for (int cg=0;cg<8;cg++)
    *(float4*)&g_P_ga_v[(size_t)n*32+cg*4] = make_float4(o[cg*4],o[cg*4+1],o[cg*4+2],o[cg*4+3]);
}

// ---------------- f_a node MLP -> out ----------------
__global__ void __launch_bounds__(256) k_fa(
    const float* __restrict__ faW1, const float* __restrict__ fab1,
    const float* __restrict__ faW2, const float* __restrict__ fab2,
    float* __restrict__ out)
{
  __shared__ __align__(16) float s_W1[32*32];
  __shared__ __align__(16) float s_W2[32*32];
  __shared__ float s_b1[32], s_b2[32];
  for (int i=threadIdx.x;i<32*32;i+=256){ s_W1[i]=faW1[14*32+i]; s_W2[i]=faW2[i]; }
  if (threadIdx.x<32){ s_b1[threadIdx.x]=fab1[threadIdx.x]; s_b2[threadIdx.x]=fab2[threadIdx.x]; }
  __syncthreads();
  int n = blockIdx.x*256 + threadIdx.x;
  if (n >= N_A) return;
  float ig = 1.f/fmaxf(g_cnt_ga[n],1.f);
  float h[32];
#pragma unroll
  for (int c=0;c<32;c++) h[c] = g_P_fa_a[(size_t)n*32+c] + s_b1[c];
#pragma unroll 4
  for (int k=0;k<32;k++){
    float g = g_acc_ga[(size_t)n*32+k]*ig;
#pragma unroll
    for (int cg=0;cg<8;cg++){
      float4 w = *(const float4*)&s_W1[k*32+cg*4];
      h[cg*4+0]+=g*w.x; h[cg*4+1]+=g*w.y; h[cg*4+2]+=g*w.z; h[cg*4+3]+=g*w.w;
    }
  }
#pragma unroll
  for (int c=0;c<32;c++) h[c]=fmaxf(h[c],0.f);
  float v[32];
#pragma unroll
  for (int c=0;c<32;c++) v[c]=s_b2[c];
#pragma unroll 4
  for (int k=0;k<32;k++){
    float g = h[k];
#pragma unroll
    for (int cg=0;cg<8;cg++){
      float4 w = *(const float4*)&s_W2[k*32+cg*4];
      v[cg*4+0]+=g*w.x; v[cg*4+1]+=g*w.y; v[cg*4+2]+=g*w.z; v[cg*4+3]+=g*w.w;
    }
  }
#pragma unroll
  for (int cg=0;cg<8;cg++)
    *(float4*)&out[(size_t)n*32+cg*4] = make_float4(
        fmaxf(v[cg*4+0],0.f), fmaxf(v[cg*4+1],0.f),
        fmaxf(v[cg*4+2],0.f), fmaxf(v[cg*4+3],0.f));
}

extern "C" void kernel_launch(void* const* d_in, const int* in_sizes, int n_in,
                              void* d_out, int out_size)
{
  const float* x_c   = (const float*)d_in[0];
  const float* x_v   = (const float*)d_in[1];
  const float* x_a   = (const float*)d_in[2];
  const int*   c2v_s = (const int*)d_in[3];
  const int*   c2v_t = (const int*)d_in[4];
  const int*   a2v_s = (const int*)d_in[5];
  const int*   a2v_t = (const int*)d_in[6];
  const float* ea_c2v = (const float*)d_in[7];
  const float* ea_a2v = (const float*)d_in[8];
  const float* gvW1 = (const float*)d_in[9];
  const float* gvb1 = (const float*)d_in[10];
  const float* gvW2 = (const float*)d_in[11];
  const float* gvb2 = (const float*)d_in[12];
  const float* hvW1 = (const float*)d_in[13];
  const float* hvb1 = (const float*)d_in[14];
  const float* hvW2 = (const float*)d_in[15];
  const float* hvb2 = (const float*)d_in[16];
  const float* fvW1 = (const float*)d_in[17];
  const float* fvb1 = (const float*)d_in[18];
  const float* fvW2 = (const float*)d_in[19];
  const float* fvb2 = (const float*)d_in[20];
  const float* gaW1 = (const float*)d_in[21];
  const float* gab1 = (const float*)d_in[22];
  const float* gaW2 = (const float*)d_in[23];
  const float* gab2 = (const float*)d_in[24];
  const float* faW1 = (const float*)d_in[25];
  const float* fab1 = (const float*)d_in[26];
  const float* faW2 = (const float*)d_in[27];
  const float* fab2 = (const float*)d_in[28];
  float* out = (float*)d_out;

  k_zero<<<2048, 256>>>();

  // edge permutation build (sort by aggregation node)
  k_zero_cnt<<<(NB_TOT+255)/256, 256>>>();
  k_hist<<<(E_C2V+255)/256, 256>>>(c2v_t, a2v_t, a2v_s);
  k_s1<<<NSCAN_BLK, 1024>>>();
  k_s2<<<1, 256>>>();
  k_s3<<<NSCAN_BLK, 1024>>>();
  k_scatter<<<(E_C2V+255)/256, 256>>>(c2v_s, c2v_t, a2v_s, a2v_t, ea_c2v, ea_a2v);

  // projections
  k_pre3<<<(N_V+255)/256, 256>>>(x_v, N_V, 13, 3, gvW1, hvW1, fvW1, 0);
  k_pre3<<<(N_C+255)/256, 256>>>(x_c, N_C, 14, 1, gvW1 + 13*32, nullptr, nullptr, 1);
  k_pre3<<<(N_A+255)/256, 256>>>(x_a, N_A, 14, 3, hvW1 + 13*32, gaW1, faW1, 2);

  // edge passes over sorted segments (validated atomic semantics)
  k_edge<<<1024, 256>>>(E_C2V/16, 0, 0,               gvW1, 27, gvb1, gvW2, gvb2);
  k_edge<<<1024, 256>>>(E_A2V/16, 1, E_C2V,           hvW1, 27, hvb1, hvW2, hvb2);

  k_fv<<<(N_V+255)/256, 256>>>(fvW1, fvb1, fvW2, fvb2, gaW1);

  k_edge<<<1024, 256>>>(E_A2V/16, 2, E_C2V + E_A2V,   gaW1, 46, gab1, gaW2, gab2);

  k_fa<<<(N_A+255)/256, 256>>>(faW1, fab1, faW2, fab2, out);
}

// round 16
// speedup vs baseline: 3.1064x; 1.2512x over previous
#include <cuda_runtime.h>
#include <cstdint>

#define N_C 50000
#define N_V 100000
#define N_A 5000
#define E_C2V 1600000
#define E_A2V 1000000
#define NSCAN_BLK ((N_V + 1023)/1024)

__device__ __align__(16) float g_P_gv_v[N_V*32];
__device__ __align__(16) float g_P_hv_v[N_V*32];
__device__ __align__(16) float g_P_fv_v[N_V*32];
__device__ __align__(16) float g_P_ga_v[N_V*32];
__device__ __align__(16) float g_P_gv_c[N_C*32];
__device__ __align__(16) float g_P_hv_a[N_A*32];
__device__ __align__(16) float g_P_ga_a[N_A*32];
__device__ __align__(16) float g_P_fa_a[N_A*32];
__device__ __align__(16) float g_acc_gv[N_V*32];   // MEAN (nodeagg)
__device__ __align__(16) float g_acc_hv[N_V*32];   // SUM (atomic)
__device__ __align__(16) float g_acc_ga[N_A*32];   // SUM (atomic)
__device__ float g_cnt_hv[N_V];
__device__ float g_cnt_ga[N_A];
// CSR (gv only)
__device__ int   g_cnti[N_V];
__device__ int   g_rs[N_V+1];
__device__ int   g_cur[N_V];
__device__ int   g_part[NSCAN_BLK+1];
__device__ int   g_pO[E_C2V];
__device__ float g_pA[E_C2V];

static __device__ __forceinline__ unsigned f2tf(float f){
  unsigned u; asm("cvt.rna.tf32.f32 %0, %1;" : "=r"(u) : "f"(f)); return u;
}
static __device__ __forceinline__ void mma8(float d[4], const unsigned a[4],
                                            unsigned b0, unsigned b1){
  asm volatile("mma.sync.aligned.m16n8k8.row.col.f32.tf32.tf32.f32 "
      "{%0,%1,%2,%3},{%4,%5,%6,%7},{%8,%9},{%0,%1,%2,%3};"
      : "+f"(d[0]),"+f"(d[1]),"+f"(d[2]),"+f"(d[3])
      : "r"(a[0]),"r"(a[1]),"r"(a[2]),"r"(a[3]),"r"(b0),"r"(b1));
}
static __device__ __forceinline__ void red4(float* p, float a, float b, float c, float d){
  asm volatile("red.global.add.v4.f32 [%0], {%1,%2,%3,%4};"
               :: "l"(p), "f"(a), "f"(b), "f"(c), "f"(d) : "memory");
}

__global__ void k_zero(){
  int i = blockIdx.x*blockDim.x + threadIdx.x;
  int stride = gridDim.x*blockDim.x;
  float4 z = make_float4(0.f,0.f,0.f,0.f);
  for (int j=i;j<N_V*8;j+=stride) ((float4*)g_acc_hv)[j]=z;
  for (int j=i;j<N_V;j+=stride) g_cnt_hv[j]=0.f;
  for (int j=i;j<N_A*8;j+=stride) ((float4*)g_acc_ga)[j]=z;
  for (int j=i;j<N_A;j+=stride) g_cnt_ga[j]=0.f;
}

// ---------------- CSR build for gv ----------------
__global__ void k_zero_cnt(){
  int i = blockIdx.x*256 + threadIdx.x;
  if (i < N_V) g_cnti[i] = 0;
}
__global__ void k_hist(const int* __restrict__ c2v_t){
  int e = blockIdx.x*256 + threadIdx.x;
  if (e < E_C2V) atomicAdd(&g_cnti[c2v_t[e]], 1);
}
__global__ void k_s1(){
  __shared__ int s[1024];
  int t = threadIdx.x, i = blockIdx.x*1024 + t;
  s[t] = (i < N_V) ? g_cnti[i] : 0;
  __syncthreads();
  for (int off=512; off>=1; off>>=1){ if (t<off) s[t]+=s[t+off]; __syncthreads(); }
  if (t==0) g_part[blockIdx.x] = s[0];
}
__global__ void k_s2(){
  __shared__ int s[128];
  int t = threadIdx.x;
  int v = (t < NSCAN_BLK) ? g_part[t] : 0;
  s[t] = v; __syncthreads();
  for (int off=1; off<128; off<<=1){
    int y = (t>=off) ? s[t-off] : 0; __syncthreads();
    s[t] += y; __syncthreads();
  }
  if (t < NSCAN_BLK) g_part[t] = s[t] - v;
}
__global__ void k_s3(){
  __shared__ int s[1024];
  int t = threadIdx.x, i = blockIdx.x*1024 + t;
  int v = (i < N_V) ? g_cnti[i] : 0;
  s[t] = v; __syncthreads();
  for (int off=1; off<1024; off<<=1){
    int y = (t>=off) ? s[t-off] : 0; __syncthreads();
    s[t] += y; __syncthreads();
  }
  if (i < N_V){
    int start = g_part[blockIdx.x] + s[t] - v;
    g_rs[i] = start; g_cur[i] = start;
  }
  if (blockIdx.x==0 && t==0) g_rs[N_V] = E_C2V;
}
__global__ void k_scatter(const int* __restrict__ c2v_s, const int* __restrict__ c2v_t,
                          const float* __restrict__ ea_c2v){
  int e = blockIdx.x*256 + threadIdx.x;
  if (e < E_C2V){
    int p = atomicAdd(&g_cur[c2v_t[e]], 1);
    g_pO[p] = c2v_s[e]; g_pA[p] = ea_c2v[e];
  }
}

// ---------------- fused per-node projections ----------------
__global__ void __launch_bounds__(256) k_pre3(
    const float* __restrict__ x, int n_nodes, int din, int nsets,
    const float* __restrict__ Wa, const float* __restrict__ Wb,
    const float* __restrict__ Wc, int which)
{
  __shared__ float s_w[3*14*32];
  const float* Ws[3] = {Wa, Wb, Wc};
  for (int m=0;m<nsets;m++)
    for (int i=threadIdx.x;i<din*32;i+=256) s_w[m*din*32+i] = Ws[m][i];
  __syncthreads();
  int node = blockIdx.x*256 + threadIdx.x;
  if (node >= n_nodes) return;
  float xr[14];
  const float* xp = x + (size_t)node*din;
  for (int k=0;k<din;k++) xr[k]=xp[k];
  for (int m=0;m<nsets;m++){
    float* out;
    if (which == 0) out = (m==0)?g_P_gv_v:((m==1)?g_P_hv_v:g_P_fv_v);
    else if (which == 1) out = g_P_gv_c;
    else out = (m==0)?g_P_hv_a:((m==1)?g_P_ga_a:g_P_fa_a);
    float* op = out + (size_t)node*32;
#pragma unroll
    for (int cg=0;cg<8;cg++){
      float4 a = make_float4(0.f,0.f,0.f,0.f);
      for (int k=0;k<din;k++){
        float4 ww = *(const float4*)&s_w[m*din*32 + k*32+cg*4];
        a.x += xr[k]*ww.x; a.y += xr[k]*ww.y; a.z += xr[k]*ww.z; a.w += xr[k]*ww.w;
      }
      *(float4*)&op[cg*4] = a;
    }
  }
}

// ---------------- persistent-warp nodeagg for gv (hi-only B, as round 8) ----------------
__global__ void __launch_bounds__(128) k_nodeagg_gv(
    const float* __restrict__ W1, const float* __restrict__ b1,
    const float* __restrict__ W2, const float* __restrict__ b2)
{
  const int lane = threadIdx.x & 31, q = lane & 3, g = lane >> 2;
  unsigned bf[4][4][2];
#pragma unroll
  for (int k=0;k<4;k++)
#pragma unroll
    for (int n=0;n<4;n++){
      bf[k][n][0] = f2tf(W2[(8*k+q)*32 + 8*n + g]);
      bf[k][n][1] = f2tf(W2[(8*k+q+4)*32 + 8*n + g]);
    }
  float we[8], bb1[8];
#pragma unroll
  for (int k=0;k<4;k++){
    we[2*k]   = W1[27*32 + 8*k+q];
    we[2*k+1] = W1[27*32 + 8*k+q+4];
    bb1[2*k]  = b1[8*k+q];
    bb1[2*k+1]= b1[8*k+q+4];
  }
  float b2r[4][2];
#pragma unroll
  for (int n=0;n<4;n++){ b2r[n][0] = b2[8*n+2*q]; b2r[n][1] = b2[8*n+2*q+1]; }

  int warp0 = blockIdx.x*4 + (threadIdx.x>>5);
  int nw = gridDim.x*4;
  for (int node = warp0; node < N_V; node += nw){
    int rs = g_rs[node], re = g_rs[node+1];
    int deg = re - rs;
    const float* po = g_P_gv_v + (size_t)node*32;
    float own[8];
#pragma unroll
    for (int k=0;k<4;k++){ own[2*k] = po[8*k+q]; own[2*k+1] = po[8*k+q+4]; }
    float sacc[4][4];
#pragma unroll
    for (int n=0;n<4;n++){ sacc[n][0]=0.f; sacc[n][1]=0.f; sacc[n][2]=0.f; sacc[n][3]=0.f; }

    for (int base = rs; base < re; base += 16){
      int e0 = base + g, e1 = base + 8 + g;
      bool v0 = e0 < re, v1 = e1 < re;
      int o0 = g_pO[v0 ? e0 : rs];
      int o1 = g_pO[v1 ? e1 : rs];
      float at0 = v0 ? g_pA[e0] : 0.f;
      float at1 = v1 ? g_pA[e1] : 0.f;
      const float* p0 = g_P_gv_c + (size_t)o0*32;
      const float* p1 = g_P_gv_c + (size_t)o1*32;
      unsigned af[4][4];
#pragma unroll
      for (int k=0;k<4;k++){
        int c0 = 8*k+q, c1 = c0+4;
        af[k][0] = f2tf(fmaxf(own[2*k]   + p0[c0] + at0*we[2*k]   + bb1[2*k],   0.f));
        af[k][1] = f2tf(fmaxf(own[2*k]   + p1[c0] + at1*we[2*k]   + bb1[2*k],   0.f));
        af[k][2] = f2tf(fmaxf(own[2*k+1] + p0[c1] + at0*we[2*k+1] + bb1[2*k+1], 0.f));
        af[k][3] = f2tf(fmaxf(own[2*k+1] + p1[c1] + at1*we[2*k+1] + bb1[2*k+1], 0.f));
      }
#pragma unroll
      for (int n=0;n<4;n++){
        float d[4] = {0.f,0.f,0.f,0.f};
#pragma unroll
        for (int k=0;k<4;k++) mma8(d, af[k], bf[k][n][0], bf[k][n][1]);
        if (v0){ sacc[n][0] += fmaxf(d[0]+b2r[n][0],0.f); sacc[n][1] += fmaxf(d[1]+b2r[n][1],0.f); }
        if (v1){ sacc[n][2] += fmaxf(d[2]+b2r[n][0],0.f); sacc[n][3] += fmaxf(d[3]+b2r[n][1],0.f); }
      }
    }
    float inv = 1.f / (float)max(deg, 1);
    float* op2 = g_acc_gv + (size_t)node*32;
#pragma unroll
    for (int n=0;n<4;n++){
      float s0 = sacc[n][0] + sacc[n][2];
      float s1 = sacc[n][1] + sacc[n][3];
      s0 += __shfl_xor_sync(0xffffffffu, s0, 4);
      s0 += __shfl_xor_sync(0xffffffffu, s0, 8);
      s0 += __shfl_xor_sync(0xffffffffu, s0, 16);
      s1 += __shfl_xor_sync(0xffffffffu, s1, 4);
      s1 += __shfl_xor_sync(0xffffffffu, s1, 8);
      s1 += __shfl_xor_sync(0xffffffffu, s1, 16);
      if (g == 0) *(float2*)&op2[8*n+2*q] = make_float2(s0*inv, s1*inv);
    }
  }
}

// ---------------- round-5 validated edge kernel (modes 1=hv, 2=ga), unsorted ----------------
__global__ void __launch_bounds__(256) k_edge(
    int ntiles, int mode,
    const int* __restrict__ src, const int* __restrict__ tgt,
    const float* __restrict__ attr,
    const float* __restrict__ W1, int rowoff_we,
    const float* __restrict__ b1,
    const float* __restrict__ W2, const float* __restrict__ b2)
{
  const float* Ps; const float* Pt; float* acc; float* cnt;
  if (mode == 1){ Ps=g_P_hv_a; Pt=g_P_hv_v; acc=g_acc_hv; cnt=g_cnt_hv; }
  else { Ps=g_P_ga_a; Pt=g_P_ga_v; acc=g_acc_ga; cnt=g_cnt_ga; }
  const int* agg = (mode == 2) ? src : tgt;

  const int lane = threadIdx.x & 31, q = lane & 3, g = lane >> 2;
  const int lowq = (q & 1) == 0;
  const int colh = 4*(q >> 1);

  unsigned bf[4][4][2];
#pragma unroll
  for (int k=0;k<4;k++)
#pragma unroll
    for (int n=0;n<4;n++){
      bf[k][n][0] = f2tf(W2[(8*k+q)*32 + 8*n + g]);
      bf[k][n][1] = f2tf(W2[(8*k+q+4)*32 + 8*n + g]);
    }
  float we[8], bb1[8];
#pragma unroll
  for (int k=0;k<4;k++){
    we[2*k]   = W1[rowoff_we*32 + 8*k+q];
    we[2*k+1] = W1[rowoff_we*32 + 8*k+q+4];
    bb1[2*k]  = b1[8*k+q];
    bb1[2*k+1]= b1[8*k+q+4];
  }
  float b2g[2][4];
#pragma unroll
  for (int j=0;j<2;j++){
    int n = lowq ? j : 2+j;
#pragma unroll
    for (int i=0;i<4;i++) b2g[j][i] = b2[8*n + colh + i];
  }

  int warp = blockIdx.x*8 + (threadIdx.x>>5);
  int nw = gridDim.x*8;
  for (int tile = warp; tile < ntiles; tile += nw){
    int e0 = tile*16 + g, e1 = e0 + 8;
    int s0 = src[e0], t0 = tgt[e0];
    int s1 = src[e1], t1 = tgt[e1];
    float at0 = attr[e0], at1 = attr[e1];
    const float* ps0 = Ps + (size_t)s0*32; const float* pt0 = Pt + (size_t)t0*32;
    const float* ps1 = Ps + (size_t)s1*32; const float* pt1 = Pt + (size_t)t1*32;
    unsigned af[4][4];
#pragma unroll
    for (int k=0;k<4;k++){
      int c0 = 8*k+q, c1 = c0+4;
      af[k][0] = f2tf(fmaxf(pt0[c0]+ps0[c0]+at0*we[2*k]+bb1[2*k], 0.f));
      af[k][1] = f2tf(fmaxf(pt1[c0]+ps1[c0]+at1*we[2*k]+bb1[2*k], 0.f));
      af[k][2] = f2tf(fmaxf(pt0[c1]+ps0[c1]+at0*we[2*k+1]+bb1[2*k+1], 0.f));
      af[k][3] = f2tf(fmaxf(pt1[c1]+ps1[c1]+at1*we[2*k+1]+bb1[2*k+1], 0.f));
    }
    float d[4][4];
#pragma unroll
    for (int n=0;n<4;n++){
      d[n][0]=0.f; d[n][1]=0.f; d[n][2]=0.f; d[n][3]=0.f;
#pragma unroll
      for (int k=0;k<4;k++) mma8(d[n], af[k], bf[k][n][0], bf[k][n][1]);
    }
    float sh[4][4];
#pragma unroll
    for (int n=0;n<4;n++)
#pragma unroll
      for (int j=0;j<4;j++) sh[n][j] = __shfl_xor_sync(0xffffffffu, d[n][j], 1);

    int i0 = (mode==2)?s0:t0, i1 = (mode==2)?s1:t1;
    float* a0 = acc + (size_t)i0*32;
    float* a1 = acc + (size_t)i1*32;
#pragma unroll
    for (int j=0;j<2;j++){
      int n = lowq ? j : 2+j;
      int c = 8*n + colh;
      float v0,v1,v2,v3, w0,w1,w2,w3;
      if (lowq){ v0=d[n][0]; v1=d[n][1]; v2=sh[n][0]; v3=sh[n][1];
                 w0=d[n][2]; w1=d[n][3]; w2=sh[n][2]; w3=sh[n][3]; }
      else     { v0=sh[n][0]; v1=sh[n][1]; v2=d[n][0]; v3=d[n][1];
                 w0=sh[n][2]; w1=sh[n][3]; w2=d[n][2]; w3=d[n][3]; }
      red4(a0 + c, fmaxf(v0+b2g[j][0],0.f), fmaxf(v1+b2g[j][1],0.f),
                   fmaxf(v2+b2g[j][2],0.f), fmaxf(v3+b2g[j][3],0.f));
      red4(a1 + c, fmaxf(w0+b2g[j][0],0.f), fmaxf(w1+b2g[j][1],0.f),
                   fmaxf(w2+b2g[j][2],0.f), fmaxf(w3+b2g[j][3],0.f));
    }
    if (lane < 16) atomicAdd(cnt + agg[tile*16+lane], 1.0f);
  }
}

// ---------------- f_v (gv mean direct, hv sum/cnt) fused with g_a projection ----------------
__global__ void __launch_bounds__(256) k_fv(
    const float* __restrict__ fvW1, const float* __restrict__ fvb1,
    const float* __restrict__ fvW2, const float* __restrict__ fvb2,
    const float* __restrict__ gaW1)
{
  __shared__ __align__(16) float s_W1[64*32];
  __shared__ __align__(16) float s_W2[32*32];
  __shared__ __align__(16) float s_Wg[32*32];
  __shared__ float s_b1[32], s_b2[32];
  for (int i=threadIdx.x;i<64*32;i+=256) s_W1[i]=fvW1[13*32+i];
  for (int i=threadIdx.x;i<32*32;i+=256){ s_W2[i]=fvW2[i]; s_Wg[i]=gaW1[14*32+i]; }
  if (threadIdx.x<32){ s_b1[threadIdx.x]=fvb1[threadIdx.x]; s_b2[threadIdx.x]=fvb2[threadIdx.x]; }
  __syncthreads();
  int n = blockIdx.x*256 + threadIdx.x;
  if (n >= N_V) return;
  float ih = 1.f/fmaxf(g_cnt_hv[n],1.f);
  float h[32];
#pragma unroll
  for (int c=0;c<32;c++) h[c] = g_P_fv_v[(size_t)n*32+c] + s_b1[c];
#pragma unroll 4
  for (int k=0;k<32;k++){
    float g = g_acc_gv[(size_t)n*32+k];
#pragma unroll
    for (int cg=0;cg<8;cg++){
      float4 w = *(const float4*)&s_W1[k*32+cg*4];
      h[cg*4+0]+=g*w.x; h[cg*4+1]+=g*w.y; h[cg*4+2]+=g*w.z; h[cg*4+3]+=g*w.w;
    }
  }
#pragma unroll 4
  for (int k=0;k<32;k++){
    float g = g_acc_hv[(size_t)n*32+k]*ih;
#pragma unroll
    for (int cg=0;cg<8;cg++){
      float4 w = *(const float4*)&s_W1[(32+k)*32+cg*4];
      h[cg*4+0]+=g*w.x; h[cg*4+1]+=g*w.y; h[cg*4+2]+=g*w.z; h[cg*4+3]+=g*w.w;
    }
  }
#pragma unroll
  for (int c=0;c<32;c++) h[c]=fmaxf(h[c],0.f);
  float v[32];
#pragma unroll
  for (int c=0;c<32;c++) v[c]=s_b2[c];
#pragma unroll 4
  for (int k=0;k<32;k++){
    float g = h[k];
#pragma unroll
    for (int cg=0;cg<8;cg++){
      float4 w = *(const float4*)&s_W2[k*32+cg*4];
      v[cg*4+0]+=g*w.x; v[cg*4+1]+=g*w.y; v[cg*4+2]+=g*w.z; v[cg*4+3]+=g*w.w;
    }
  }
#pragma unroll
  for (int c=0;c<32;c++) v[c]=fmaxf(v[c],0.f);
  float o[32];
#pragma unroll
  for (int c=0;c<32;c++) o[c]=0.f;
#pragma unroll 4
  for (int k=0;k<32;k++){
    float g = v[k];
#pragma unroll
    for (int cg=0;cg<8;cg++){
      float4 w = *(const float4*)&s_Wg[k*32+cg*4];
      o[cg*4+0]+=g*w.x; o[cg*4+1]+=g*w.y; o[cg*4+2]+=g*w.z; o[cg*4+3]+=g*w.w;
    }
  }
#pragma unroll
  for (int cg=0;cg<8;cg++)
    *(float4*)&g_P_ga_v[(size_t)n*32+cg*4] = make_float4(o[cg*4],o[cg*4+1],o[cg*4+2],o[cg*4+3]);
}

// ---------------- f_a -> out ----------------
__global__ void __launch_bounds__(256) k_fa(
    const float* __restrict__ faW1, const float* __restrict__ fab1,
    const float* __restrict__ faW2, const float* __restrict__ fab2,
    float* __restrict__ out)
{
  __shared__ __align__(16) float s_W1[32*32];
  __shared__ __align__(16) float s_W2[32*32];
  __shared__ float s_b1[32], s_b2[32];
  for (int i=threadIdx.x;i<32*32;i+=256){ s_W1[i]=faW1[14*32+i]; s_W2[i]=faW2[i]; }
  if (threadIdx.x<32){ s_b1[threadIdx.x]=fab1[threadIdx.x]; s_b2[threadIdx.x]=fab2[threadIdx.x]; }
  __syncthreads();
  int n = blockIdx.x*256 + threadIdx.x;
  if (n >= N_A) return;
  float ig = 1.f/fmaxf(g_cnt_ga[n],1.f);
  float h[32];
#pragma unroll
  for (int c=0;c<32;c++) h[c] = g_P_fa_a[(size_t)n*32+c] + s_b1[c];
#pragma unroll 4
  for (int k=0;k<32;k++){
    float g = g_acc_ga[(size_t)n*32+k]*ig;
#pragma unroll
    for (int cg=0;cg<8;cg++){
      float4 w = *(const float4*)&s_W1[k*32+cg*4];
      h[cg*4+0]+=g*w.x; h[cg*4+1]+=g*w.y; h[cg*4+2]+=g*w.z; h[cg*4+3]+=g*w.w;
    }
  }
#pragma unroll
  for (int c=0;c<32;c++) h[c]=fmaxf(h[c],0.f);
  float v[32];
#pragma unroll
  for (int c=0;c<32;c++) v[c]=s_b2[c];
#pragma unroll 4
  for (int k=0;k<32;k++){
    float g = h[k];
#pragma unroll
    for (int cg=0;cg<8;cg++){
      float4 w = *(const float4*)&s_W2[k*32+cg*4];
      v[cg*4+0]+=g*w.x; v[cg*4+1]+=g*w.y; v[cg*4+2]+=g*w.z; v[cg*4+3]+=g*w.w;
    }
  }
#pragma unroll
  for (int cg=0;cg<8;cg++)
    *(float4*)&out[(size_t)n*32+cg*4] = make_float4(
        fmaxf(v[cg*4+0],0.f), fmaxf(v[cg*4+1],0.f),
        fmaxf(v[cg*4+2],0.f), fmaxf(v[cg*4+3],0.f));
}

extern "C" void kernel_launch(void* const* d_in, const int* in_sizes, int n_in,
                              void* d_out, int out_size)
{
  const float* x_c   = (const float*)d_in[0];
  const float* x_v   = (const float*)d_in[1];
  const float* x_a   = (const float*)d_in[2];
  const int*   c2v_s = (const int*)d_in[3];
  const int*   c2v_t = (const int*)d_in[4];
  const int*   a2v_s = (const int*)d_in[5];
  const int*   a2v_t = (const int*)d_in[6];
  const float* ea_c2v = (const float*)d_in[7];
  const float* ea_a2v = (const float*)d_in[8];
  const float* gvW1 = (const float*)d_in[9];
  const float* gvb1 = (const float*)d_in[10];
  const float* gvW2 = (const float*)d_in[11];
  const float* gvb2 = (const float*)d_in[12];
  const float* hvW1 = (const float*)d_in[13];
  const float* hvb1 = (const float*)d_in[14];
  const float* hvW2 = (const float*)d_in[15];
  const float* hvb2 = (const float*)d_in[16];
  const float* fvW1 = (const float*)d_in[17];
  const float* fvb1 = (const float*)d_in[18];
  const float* fvW2 = (const float*)d_in[19];
  const float* fvb2 = (const float*)d_in[20];
  const float* gaW1 = (const float*)d_in[21];
  const float* gab1 = (const float*)d_in[22];
  const float* gaW2 = (const float*)d_in[23];
  const float* gab2 = (const float*)d_in[24];
  const float* faW1 = (const float*)d_in[25];
  const float* fab1 = (const float*)d_in[26];
  const float* faW2 = (const float*)d_in[27];
  const float* fab2 = (const float*)d_in[28];
  float* out = (float*)d_out;

  k_zero<<<1024, 256>>>();

  // CSR build for gv
  k_zero_cnt<<<(N_V+255)/256, 256>>>();
  k_hist<<<(E_C2V+255)/256, 256>>>(c2v_t);
  k_s1<<<NSCAN_BLK, 1024>>>();
  k_s2<<<1, 128>>>();
  k_s3<<<NSCAN_BLK, 1024>>>();
  k_scatter<<<(E_C2V+255)/256, 256>>>(c2v_s, c2v_t, ea_c2v);

  // projections
  k_pre3<<<(N_V+255)/256, 256>>>(x_v, N_V, 13, 3, gvW1, hvW1, fvW1, 0);
  k_pre3<<<(N_C+255)/256, 256>>>(x_c, N_C, 14, 1, gvW1 + 13*32, nullptr, nullptr, 1);
  k_pre3<<<(N_A+255)/256, 256>>>(x_a, N_A, 14, 3, hvW1 + 13*32, gaW1, faW1, 2);

  // gv: persistent-warp register aggregation (no atomics)
  k_nodeagg_gv<<<2048, 128>>>(gvW1, gvb1, gvW2, gvb2);
  // hv: validated atomic path (unsorted)
  k_edge<<<1024, 256>>>(E_A2V/16, 1, a2v_s, a2v_t, ea_a2v, hvW1, 27, hvb1, hvW2, hvb2);

  k_fv<<<(N_V+255)/256, 256>>>(fvW1, fvb1, fvW2, fvb2, gaW1);

  // ga: validated atomic path (unsorted)
  k_edge<<<1024, 256>>>(E_A2V/16, 2, a2v_s, a2v_t, ea_a2v, gaW1, 46, gab1, gaW2, gab2);

  k_fa<<<(N_A+255)/256, 256>>>(faW1, fab1, faW2, fab2, out);
}

// round 17
// speedup vs baseline: 3.1691x; 1.0202x over previous
#include <cuda_runtime.h>
#include <cstdint>

#define N_C 50000
#define N_V 100000
#define N_A 5000
#define E_C2V 1600000
#define E_A2V 1000000
#define NB (N_V + N_A)                 // bins: gv(t) | ga(s)
#define EP (E_C2V + E_A2V)             // permuted entries
#define NSCAN_BLK ((NB + 1023)/1024)

__device__ __align__(16) float g_P_gv_v[N_V*32];
__device__ __align__(16) float g_P_hv_v[N_V*32];
__device__ __align__(16) float g_P_fv_v[N_V*32];
__device__ __align__(16) float g_P_ga_v[N_V*32];
__device__ __align__(16) float g_P_gv_c[N_C*32];
__device__ __align__(16) float g_P_hv_a[N_A*32];
__device__ __align__(16) float g_P_ga_a[N_A*32];
__device__ __align__(16) float g_P_fa_a[N_A*32];
__device__ __align__(16) float g_acc_gv[N_V*32];   // MEAN (nodeagg)
__device__ __align__(16) float g_acc_hv[N_V*32];   // SUM (atomic)
__device__ __align__(16) float g_acc_ga[N_A*32];   // MEAN (nodeagg)
__device__ float g_cnt_hv[N_V];
// CSR (gv | ga)
__device__ int   g_cnti[NB];
__device__ int   g_rs[NB+1];
__device__ int   g_cur[NB];
__device__ int   g_part[NSCAN_BLK+1];
__device__ int   g_pO[EP];
__device__ float g_pA[EP];

static __device__ __forceinline__ unsigned f2tf(float f){
  unsigned u; asm("cvt.rna.tf32.f32 %0, %1;" : "=r"(u) : "f"(f)); return u;
}
static __device__ __forceinline__ void mma8(float d[4], const unsigned a[4],
                                            unsigned b0, unsigned b1){
  asm volatile("mma.sync.aligned.m16n8k8.row.col.f32.tf32.tf32.f32 "
      "{%0,%1,%2,%3},{%4,%5,%6,%7},{%8,%9},{%0,%1,%2,%3};"
      : "+f"(d[0]),"+f"(d[1]),"+f"(d[2]),"+f"(d[3])
      : "r"(a[0]),"r"(a[1]),"r"(a[2]),"r"(a[3]),"r"(b0),"r"(b1));
}
static __device__ __forceinline__ void red4(float* p, float a, float b, float c, float d){
  asm volatile("red.global.add.v4.f32 [%0], {%1,%2,%3,%4};"
               :: "l"(p), "f"(a), "f"(b), "f"(c), "f"(d) : "memory");
}

__global__ void k_zero(){
  int i = blockIdx.x*blockDim.x + threadIdx.x;
  int stride = gridDim.x*blockDim.x;
  float4 z = make_float4(0.f,0.f,0.f,0.f);
  for (int j=i;j<N_V*8;j+=stride) ((float4*)g_acc_hv)[j]=z;
  for (int j=i;j<N_V;j+=stride) g_cnt_hv[j]=0.f;
}

// ---------------- CSR build: bins gv [0,N_V) | ga [N_V,N_V+N_A) ----------------
__global__ void k_zero_cnt(){
  int i = blockIdx.x*256 + threadIdx.x;
  if (i < NB) g_cnti[i] = 0;
}
__global__ void k_hist(const int* __restrict__ c2v_t, const int* __restrict__ a2v_s){
  int e = blockIdx.x*256 + threadIdx.x;
  if (e < E_A2V) atomicAdd(&g_cnti[N_V + a2v_s[e]], 1);
  if (e < E_C2V) atomicAdd(&g_cnti[c2v_t[e]], 1);
}
__global__ void k_s1(){
  __shared__ int s[1024];
  int t = threadIdx.x, i = blockIdx.x*1024 + t;
  s[t] = (i < NB) ? g_cnti[i] : 0;
  __syncthreads();
  for (int off=512; off>=1; off>>=1){ if (t<off) s[t]+=s[t+off]; __syncthreads(); }
  if (t==0) g_part[blockIdx.x] = s[0];
}
__global__ void k_s2(){
  __shared__ int s[128];
  int t = threadIdx.x;
  int v = (t < NSCAN_BLK) ? g_part[t] : 0;
  s[t] = v; __syncthreads();
  for (int off=1; off<128; off<<=1){
    int y = (t>=off) ? s[t-off] : 0; __syncthreads();
    s[t] += y; __syncthreads();
  }
  if (t < NSCAN_BLK) g_part[t] = s[t] - v;
}
__global__ void k_s3(){
  __shared__ int s[1024];
  int t = threadIdx.x, i = blockIdx.x*1024 + t;
  int v = (i < NB) ? g_cnti[i] : 0;
  s[t] = v; __syncthreads();
  for (int off=1; off<1024; off<<=1){
    int y = (t>=off) ? s[t-off] : 0; __syncthreads();
    s[t] += y; __syncthreads();
  }
  if (i < NB){
    int start = g_part[blockIdx.x] + s[t] - v;
    g_rs[i] = start; g_cur[i] = start;
  }
  if (blockIdx.x==0 && t==0) g_rs[NB] = EP;
}
__global__ void k_scatter(const int* __restrict__ c2v_s, const int* __restrict__ c2v_t,
                          const int* __restrict__ a2v_s, const int* __restrict__ a2v_t,
                          const float* __restrict__ ea_c2v, const float* __restrict__ ea_a2v){
  int e = blockIdx.x*256 + threadIdx.x;
  if (e < E_A2V){
    int p = atomicAdd(&g_cur[N_V + a2v_s[e]], 1);
    g_pO[p] = a2v_t[e]; g_pA[p] = ea_a2v[e];
  }
  if (e < E_C2V){
    int p = atomicAdd(&g_cur[c2v_t[e]], 1);
    g_pO[p] = c2v_s[e]; g_pA[p] = ea_c2v[e];
  }
}

// ---------------- fused per-node projections ----------------
__global__ void __launch_bounds__(256) k_pre3(
    const float* __restrict__ x, int n_nodes, int din, int nsets,
    const float* __restrict__ Wa, const float* __restrict__ Wb,
    const float* __restrict__ Wc, int which)
{
  __shared__ float s_w[3*14*32];
  const float* Ws[3] = {Wa, Wb, Wc};
  for (int m=0;m<nsets;m++)
    for (int i=threadIdx.x;i<din*32;i+=256) s_w[m*din*32+i] = Ws[m][i];
  __syncthreads();
  int node = blockIdx.x*256 + threadIdx.x;
  if (node >= n_nodes) return;
  float xr[14];
  const float* xp = x + (size_t)node*din;
  for (int k=0;k<din;k++) xr[k]=xp[k];
  for (int m=0;m<nsets;m++){
    float* out;
    if (which == 0) out = (m==0)?g_P_gv_v:((m==1)?g_P_hv_v:g_P_fv_v);
    else if (which == 1) out = g_P_gv_c;
    else out = (m==0)?g_P_hv_a:((m==1)?g_P_ga_a:g_P_fa_a);
    float* op = out + (size_t)node*32;
#pragma unroll
    for (int cg=0;cg<8;cg++){
      float4 a = make_float4(0.f,0.f,0.f,0.f);
      for (int k=0;k<din;k++){
        float4 ww = *(const float4*)&s_w[m*din*32 + k*32+cg*4];
        a.x += xr[k]*ww.x; a.y += xr[k]*ww.y; a.z += xr[k]*ww.z; a.w += xr[k]*ww.w;
      }
      *(float4*)&op[cg*4] = a;
    }
  }
}

// ---------------- persistent-warp nodeagg for gv (round-16 validated, verbatim) ----------------
__global__ void __launch_bounds__(128) k_nodeagg_gv(
    const float* __restrict__ W1, const float* __restrict__ b1,
    const float* __restrict__ W2, const float* __restrict__ b2)
{
  const int lane = threadIdx.x & 31, q = lane & 3, g = lane >> 2;
  unsigned bf[4][4][2];
#pragma unroll
  for (int k=0;k<4;k++)
#pragma unroll
    for (int n=0;n<4;n++){
      bf[k][n][0] = f2tf(W2[(8*k+q)*32 + 8*n + g]);
      bf[k][n][1] = f2tf(W2[(8*k+q+4)*32 + 8*n + g]);
    }
  float we[8], bb1[8];
#pragma unroll
  for (int k=0;k<4;k++){
    we[2*k]   = W1[27*32 + 8*k+q];
    we[2*k+1] = W1[27*32 + 8*k+q+4];
    bb1[2*k]  = b1[8*k+q];
    bb1[2*k+1]= b1[8*k+q+4];
  }
  float b2r[4][2];
#pragma unroll
  for (int n=0;n<4;n++){ b2r[n][0] = b2[8*n+2*q]; b2r[n][1] = b2[8*n+2*q+1]; }

  int warp0 = blockIdx.x*4 + (threadIdx.x>>5);
  int nw = gridDim.x*4;
  for (int node = warp0; node < N_V; node += nw){
    int rs = g_rs[node], re = g_rs[node+1];
    int deg = re - rs;
    const float* po = g_P_gv_v + (size_t)node*32;
    float own[8];
#pragma unroll
    for (int k=0;k<4;k++){ own[2*k] = po[8*k+q]; own[2*k+1] = po[8*k+q+4]; }
    float sacc[4][4];
#pragma unroll
    for (int n=0;n<4;n++){ sacc[n][0]=0.f; sacc[n][1]=0.f; sacc[n][2]=0.f; sacc[n][3]=0.f; }

    for (int base = rs; base < re; base += 16){
      int e0 = base + g, e1 = base + 8 + g;
      bool v0 = e0 < re, v1 = e1 < re;
      int o0 = g_pO[v0 ? e0 : rs];
      int o1 = g_pO[v1 ? e1 : rs];
      float at0 = v0 ? g_pA[e0] : 0.f;
      float at1 = v1 ? g_pA[e1] : 0.f;
      const float* p0 = g_P_gv_c + (size_t)o0*32;
      const float* p1 = g_P_gv_c + (size_t)o1*32;
      unsigned af[4][4];
#pragma unroll
      for (int k=0;k<4;k++){
        int c0 = 8*k+q, c1 = c0+4;
        af[k][0] = f2tf(fmaxf(own[2*k]   + p0[c0] + at0*we[2*k]   + bb1[2*k],   0.f));
        af[k][1] = f2tf(fmaxf(own[2*k]   + p1[c0] + at1*we[2*k]   + bb1[2*k],   0.f));
        af[k][2] = f2tf(fmaxf(own[2*k+1] + p0[c1] + at0*we[2*k+1] + bb1[2*k+1], 0.f));
        af[k][3] = f2tf(fmaxf(own[2*k+1] + p1[c1] + at1*we[2*k+1] + bb1[2*k+1], 0.f));
      }
#pragma unroll
      for (int n=0;n<4;n++){
        float d[4] = {0.f,0.f,0.f,0.f};
#pragma unroll
        for (int k=0;k<4;k++) mma8(d, af[k], bf[k][n][0], bf[k][n][1]);
        if (v0){ sacc[n][0] += fmaxf(d[0]+b2r[n][0],0.f); sacc[n][1] += fmaxf(d[1]+b2r[n][1],0.f); }
        if (v1){ sacc[n][2] += fmaxf(d[2]+b2r[n][0],0.f); sacc[n][3] += fmaxf(d[3]+b2r[n][1],0.f); }
      }
    }
    float inv = 1.f / (float)max(deg, 1);
    float* op2 = g_acc_gv + (size_t)node*32;
#pragma unroll
    for (int n=0;n<4;n++){
      float s0 = sacc[n][0] + sacc[n][2];
      float s1 = sacc[n][1] + sacc[n][3];
      s0 += __shfl_xor_sync(0xffffffffu, s0, 4);
      s0 += __shfl_xor_sync(0xffffffffu, s0, 8);
      s0 += __shfl_xor_sync(0xffffffffu, s0, 16);
      s1 += __shfl_xor_sync(0xffffffffu, s1, 4);
      s1 += __shfl_xor_sync(0xffffffffu, s1, 8);
      s1 += __shfl_xor_sync(0xffffffffu, s1, 16);
      if (g == 0) *(float2*)&op2[8*n+2*q] = make_float2(s0*inv, s1*inv);
    }
  }
}

// ---------------- persistent-warp nodeagg for ga (clone; bins at N_V+, deg≈200) ----------------
__global__ void __launch_bounds__(128) k_nodeagg_ga(
    const float* __restrict__ W1, const float* __restrict__ b1,
    const float* __restrict__ W2, const float* __restrict__ b2)
{
  const int lane = threadIdx.x & 31, q = lane & 3, g = lane >> 2;
  unsigned bf[4][4][2];
#pragma unroll
  for (int k=0;k<4;k++)
#pragma unroll
    for (int n=0;n<4;n++){
      bf[k][n][0] = f2tf(W2[(8*k+q)*32 + 8*n + g]);
      bf[k][n][1] = f2tf(W2[(8*k+q+4)*32 + 8*n + g]);
    }
  float we[8], bb1[8];
#pragma unroll
  for (int k=0;k<4;k++){
    we[2*k]   = W1[46*32 + 8*k+q];
    we[2*k+1] = W1[46*32 + 8*k+q+4];
    bb1[2*k]  = b1[8*k+q];
    bb1[2*k+1]= b1[8*k+q+4];
  }
  float b2r[4][2];
#pragma unroll
  for (int n=0;n<4;n++){ b2r[n][0] = b2[8*n+2*q]; b2r[n][1] = b2[8*n+2*q+1]; }

  int warp0 = blockIdx.x*4 + (threadIdx.x>>5);
  int nw = gridDim.x*4;
  for (int node = warp0; node < N_A; node += nw){
    int rs = g_rs[N_V+node], re = g_rs[N_V+node+1];
    int deg = re - rs;
    const float* po = g_P_ga_a + (size_t)node*32;
    float own[8];
#pragma unroll
    for (int k=0;k<4;k++){ own[2*k] = po[8*k+q]; own[2*k+1] = po[8*k+q+4]; }
    float sacc[4][4];
#pragma unroll
    for (int n=0;n<4;n++){ sacc[n][0]=0.f; sacc[n][1]=0.f; sacc[n][2]=0.f; sacc[n][3]=0.f; }

    for (int base = rs; base < re; base += 16){
      int e0 = base + g, e1 = base + 8 + g;
      bool v0 = e0 < re, v1 = e1 < re;
      int o0 = g_pO[v0 ? e0 : rs];
      int o1 = g_pO[v1 ? e1 : rs];
      float at0 = v0 ? g_pA[e0] : 0.f;
      float at1 = v1 ? g_pA[e1] : 0.f;
      const float* p0 = g_P_ga_v + (size_t)o0*32;
      const float* p1 = g_P_ga_v + (size_t)o1*32;
      unsigned af[4][4];
#pragma unroll
      for (int k=0;k<4;k++){
        int c0 = 8*k+q, c1 = c0+4;
        af[k][0] = f2tf(fmaxf(own[2*k]   + p0[c0] + at0*we[2*k]   + bb1[2*k],   0.f));
        af[k][1] = f2tf(fmaxf(own[2*k]   + p1[c0] + at1*we[2*k]   + bb1[2*k],   0.f));
        af[k][2] = f2tf(fmaxf(own[2*k+1] + p0[c1] + at0*we[2*k+1] + bb1[2*k+1], 0.f));
        af[k][3] = f2tf(fmaxf(own[2*k+1] + p1[c1] + at1*we[2*k+1] + bb1[2*k+1], 0.f));
      }
#pragma unroll
      for (int n=0;n<4;n++){
        float d[4] = {0.f,0.f,0.f,0.f};
#pragma unroll
        for (int k=0;k<4;k++) mma8(d, af[k], bf[k][n][0], bf[k][n][1]);
        if (v0){ sacc[n][0] += fmaxf(d[0]+b2r[n][0],0.f); sacc[n][1] += fmaxf(d[1]+b2r[n][1],0.f); }
        if (v1){ sacc[n][2] += fmaxf(d[2]+b2r[n][0],0.f); sacc[n][3] += fmaxf(d[3]+b2r[n][1],0.f); }
      }
    }
    float inv = 1.f / (float)max(deg, 1);
    float* op2 = g_acc_ga + (size_t)node*32;
#pragma unroll
    for (int n=0;n<4;n++){
      float s0 = sacc[n][0] + sacc[n][2];
      float s1 = sacc[n][1] + sacc[n][3];
      s0 += __shfl_xor_sync(0xffffffffu, s0, 4);
      s0 += __shfl_xor_sync(0xffffffffu, s0, 8);
      s0 += __shfl_xor_sync(0xffffffffu, s0, 16);
      s1 += __shfl_xor_sync(0xffffffffu, s1, 4);
      s1 += __shfl_xor_sync(0xffffffffu, s1, 8);
      s1 += __shfl_xor_sync(0xffffffffu, s1, 16);
      if (g == 0) *(float2*)&op2[8*n+2*q] = make_float2(s0*inv, s1*inv);
    }
  }
}

// ---------------- hv: validated atomic edge kernel ----------------
__global__ void __launch_bounds__(256) k_edge_hv(
    int ntiles,
    const int* __restrict__ src, const int* __restrict__ tgt,
    const float* __restrict__ attr,
    const float* __restrict__ W1, const float* __restrict__ b1,
    const float* __restrict__ W2, const float* __restrict__ b2)
{
  const float* Ps = g_P_hv_a; const float* Pt = g_P_hv_v;
  float* acc = g_acc_hv; float* cnt = g_cnt_hv;
  const int lane = threadIdx.x & 31, q = lane & 3, g = lane >> 2;
  const int lowq = (q & 1) == 0;
  const int colh = 4*(q >> 1);

  unsigned bf[4][4][2];
#pragma unroll
  for (int k=0;k<4;k++)
#pragma unroll
    for (int n=0;n<4;n++){
      bf[k][n][0] = f2tf(W2[(8*k+q)*32 + 8*n + g]);
      bf[k][n][1] = f2tf(W2[(8*k+q+4)*32 + 8*n + g]);
    }
  float we[8], bb1[8];
#pragma unroll
  for (int k=0;k<4;k++){
    we[2*k]   = W1[27*32 + 8*k+q];
    we[2*k+1] = W1[27*32 + 8*k+q+4];
    bb1[2*k]  = b1[8*k+q];
    bb1[2*k+1]= b1[8*k+q+4];
  }
  float b2g[2][4];
#pragma unroll
  for (int j=0;j<2;j++){
    int n = lowq ? j : 2+j;
#pragma unroll
    for (int i=0;i<4;i++) b2g[j][i] = b2[8*n + colh + i];
  }

  int warp = blockIdx.x*8 + (threadIdx.x>>5);
  int nw = gridDim.x*8;
  for (int tile = warp; tile < ntiles; tile += nw){
    int e0 = tile*16 + g, e1 = e0 + 8;
    int s0 = src[e0], t0 = tgt[e0];
    int s1 = src[e1], t1 = tgt[e1];
    float at0 = attr[e0], at1 = attr[e1];
    const float* ps0 = Ps + (size_t)s0*32; const float* pt0 = Pt + (size_t)t0*32;
    const float* ps1 = Ps + (size_t)s1*32; const float* pt1 = Pt + (size_t)t1*32;
    unsigned af[4][4];
#pragma unroll
    for (int k=0;k<4;k++){
      int c0 = 8*k+q, c1 = c0+4;
      af[k][0] = f2tf(fmaxf(pt0[c0]+ps0[c0]+at0*we[2*k]+bb1[2*k], 0.f));
      af[k][1] = f2tf(fmaxf(pt1[c0]+ps1[c0]+at1*we[2*k]+bb1[2*k], 0.f));
      af[k][2] = f2tf(fmaxf(pt0[c1]+ps0[c1]+at0*we[2*k+1]+bb1[2*k+1], 0.f));
      af[k][3] = f2tf(fmaxf(pt1[c1]+ps1[c1]+at1*we[2*k+1]+bb1[2*k+1], 0.f));
    }
    float d[4][4];
#pragma unroll
    for (int n=0;n<4;n++){
      d[n][0]=0.f; d[n][1]=0.f; d[n][2]=0.f; d[n][3]=0.f;
#pragma unroll
      for (int k=0;k<4;k++) mma8(d[n], af[k], bf[k][n][0], bf[k][n][1]);
    }
    float sh[4][4];
#pragma unroll
    for (int n=0;n<4;n++)
#pragma unroll
      for (int j=0;j<4;j++) sh[n][j] = __shfl_xor_sync(0xffffffffu, d[n][j], 1);

    float* a0 = acc + (size_t)t0*32;
    float* a1 = acc + (size_t)t1*32;
#pragma unroll
    for (int j=0;j<2;j++){
      int n = lowq ? j : 2+j;
      int c = 8*n + colh;
      float v0,v1,v2,v3, w0,w1,w2,w3;
      if (lowq){ v0=d[n][0]; v1=d[n][1]; v2=sh[n][0]; v3=sh[n][1];
                 w0=d[n][2]; w1=d[n][3]; w2=sh[n][2]; w3=sh[n][3]; }
      else     { v0=sh[n][0]; v1=sh[n][1]; v2=d[n][0]; v3=d[n][1];
                 w0=sh[n][2]; w1=sh[n][3]; w2=d[n][2]; w3=d[n][3]; }
      red4(a0 + c, fmaxf(v0+b2g[j][0],0.f), fmaxf(v1+b2g[j][1],0.f),
                   fmaxf(v2+b2g[j][2],0.f), fmaxf(v3+b2g[j][3],0.f));
      red4(a1 + c, fmaxf(w0+b2g[j][0],0.f), fmaxf(w1+b2g[j][1],0.f),
                   fmaxf(w2+b2g[j][2],0.f), fmaxf(w3+b2g[j][3],0.f));
    }
    if (lane < 16) atomicAdd(cnt + tgt[tile*16+lane], 1.0f);
  }
}

// ---------------- f_v (gv mean direct, hv sum/cnt) fused with g_a projection ----------------
__global__ void __launch_bounds__(256) k_fv(
    const float* __restrict__ fvW1, const float* __restrict__ fvb1,
    const float* __restrict__ fvW2, const float* __restrict__ fvb2,
    const float* __restrict__ gaW1)
{
  __shared__ __align__(16) float s_W1[64*32];
  __shared__ __align__(16) float s_W2[32*32];
  __shared__ __align__(16) float s_Wg[32*32];
  __shared__ float s_b1[32], s_b2[32];
  for (int i=threadIdx.x;i<64*32;i+=256) s_W1[i]=fvW1[13*32+i];
  for (int i=threadIdx.x;i<32*32;i+=256){ s_W2[i]=fvW2[i]; s_Wg[i]=gaW1[14*32+i]; }
  if (threadIdx.x<32){ s_b1[threadIdx.x]=fvb1[threadIdx.x]; s_b2[threadIdx.x]=fvb2[threadIdx.x]; }
  __syncthreads();
  int n = blockIdx.x*256 + threadIdx.x;
  if (n >= N_V) return;
  float ih = 1.f/fmaxf(g_cnt_hv[n],1.f);
  float h[32];
#pragma unroll
  for (int c=0;c<32;c++) h[c] = g_P_fv_v[(size_t)n*32+c] + s_b1[c];
#pragma unroll 4
  for (int k=0;k<32;k++){
    float g = g_acc_gv[(size_t)n*32+k];
#pragma unroll
    for (int cg=0;cg<8;cg++){
      float4 w = *(const float4*)&s_W1[k*32+cg*4];
      h[cg*4+0]+=g*w.x; h[cg*4+1]+=g*w.y; h[cg*4+2]+=g*w.z; h[cg*4+3]+=g*w.w;
    }
  }
#pragma unroll 4
  for (int k=0;k<32;k++){
    float g = g_acc_hv[(size_t)n*32+k]*ih;
#pragma unroll
    for (int cg=0;cg<8;cg++){
      float4 w = *(const float4*)&s_W1[(32+k)*32+cg*4];
      h[cg*4+0]+=g*w.x; h[cg*4+1]+=g*w.y; h[cg*4+2]+=g*w.z; h[cg*4+3]+=g*w.w;
    }
  }
#pragma unroll
  for (int c=0;c<32;c++) h[c]=fmaxf(h[c],0.f);
  float v[32];
#pragma unroll
  for (int c=0;c<32;c++) v[c]=s_b2[c];
#pragma unroll 4
  for (int k=0;k<32;k++){
    float g = h[k];
#pragma unroll
    for (int cg=0;cg<8;cg++){
      float4 w = *(const float4*)&s_W2[k*32+cg*4];
      v[cg*4+0]+=g*w.x; v[cg*4+1]+=g*w.y; v[cg*4+2]+=g*w.z; v[cg*4+3]+=g*w.w;
    }
  }
#pragma unroll
  for (int c=0;c<32;c++) v[c]=fmaxf(v[c],0.f);
  float o[32];
#pragma unroll
  for (int c=0;c<32;c++) o[c]=0.f;
#pragma unroll 4
  for (int k=0;k<32;k++){
    float g = v[k];
#pragma unroll
    for (int cg=0;cg<8;cg++){
      float4 w = *(const float4*)&s_Wg[k*32+cg*4];
      o[cg*4+0]+=g*w.x; o[cg*4+1]+=g*w.y; o[cg*4+2]+=g*w.z; o[cg*4+3]+=g*w.w;
    }
  }
#pragma unroll
  for (int cg=0;cg<8;cg++)
    *(float4*)&g_P_ga_v[(size_t)n*32+cg*4] = make_float4(o[cg*4],o[cg*4+1],o[cg*4+2],o[cg*4+3]);
}

// ---------------- f_a -> out (ga mean direct) ----------------
__global__ void __launch_bounds__(256) k_fa(
    const float* __restrict__ faW1, const float* __restrict__ fab1,
    const float* __restrict__ faW2, const float* __restrict__ fab2,
    float* __restrict__ out)
{
  __shared__ __align__(16) float s_W1[32*32];
  __shared__ __align__(16) float s_W2[32*32];
  __shared__ float s_b1[32], s_b2[32];
  for (int i=threadIdx.x;i<32*32;i+=256){ s_W1[i]=faW1[14*32+i]; s_W2[i]=faW2[i]; }
  if (threadIdx.x<32){ s_b1[threadIdx.x]=fab1[threadIdx.x]; s_b2[threadIdx.x]=fab2[threadIdx.x]; }
  __syncthreads();
  int n = blockIdx.x*256 + threadIdx.x;
  if (n >= N_A) return;
  float h[32];
#pragma unroll
  for (int c=0;c<32;c++) h[c] = g_P_fa_a[(size_t)n*32+c] + s_b1[c];
#pragma unroll 4
  for (int k=0;k<32;k++){
    float g = g_acc_ga[(size_t)n*32+k];
#pragma unroll
    for (int cg=0;cg<8;cg++){
      float4 w = *(const float4*)&s_W1[k*32+cg*4];
      h[cg*4+0]+=g*w.x; h[cg*4+1]+=g*w.y; h[cg*4+2]+=g*w.z; h[cg*4+3]+=g*w.w;
    }
  }
#pragma unroll
  for (int c=0;c<32;c++) h[c]=fmaxf(h[c],0.f);
  float v[32];
#pragma unroll
  for (int c=0;c<32;c++) v[c]=s_b2[c];
#pragma unroll 4
  for (int k=0;k<32;k++){
    float g = h[k];
#pragma unroll
    for (int cg=0;cg<8;cg++){
      float4 w = *(const float4*)&s_W2[k*32+cg*4];
      v[cg*4+0]+=g*w.x; v[cg*4+1]+=g*w.y; v[cg*4+2]+=g*w.z; v[cg*4+3]+=g*w.w;
    }
  }
#pragma unroll
  for (int cg=0;cg<8;cg++)
    *(float4*)&out[(size_t)n*32+cg*4] = make_float4(
        fmaxf(v[cg*4+0],0.f), fmaxf(v[cg*4+1],0.f),
        fmaxf(v[cg*4+2],0.f), fmaxf(v[cg*4+3],0.f));
}

extern "C" void kernel_launch(void* const* d_in, const int* in_sizes, int n_in,
                              void* d_out, int out_size)
{
  const float* x_c   = (const float*)d_in[0];
  const float* x_v   = (const float*)d_in[1];
  const float* x_a   = (const float*)d_in[2];
  const int*   c2v_s = (const int*)d_in[3];
  const int*   c2v_t = (const int*)d_in[4];
  const int*   a2v_s = (const int*)d_in[5];
  const int*   a2v_t = (const int*)d_in[6];
  const float* ea_c2v = (const float*)d_in[7];
  const float* ea_a2v = (const float*)d_in[8];
  const float* gvW1 = (const float*)d_in[9];
  const float* gvb1 = (const float*)d_in[10];
  const float* gvW2 = (const float*)d_in[11];
  const float* gvb2 = (const float*)d_in[12];
  const float* hvW1 = (const float*)d_in[13];
  const float* hvb1 = (const float*)d_in[14];
  const float* hvW2 = (const float*)d_in[15];
  const float* hvb2 = (const float*)d_in[16];
  const float* fvW1 = (const float*)d_in[17];
  const float* fvb1 = (const float*)d_in[18];
  const float* fvW2 = (const float*)d_in[19];
  const float* fvb2 = (const float*)d_in[20];
  const float* gaW1 = (const float*)d_in[21];
  const float* gab1 = (const float*)d_in[22];
  const float* gaW2 = (const float*)d_in[23];
  const float* gab2 = (const float*)d_in[24];
  const float* faW1 = (const float*)d_in[25];
  const float* fab1 = (const float*)d_in[26];
  const float* faW2 = (const float*)d_in[27];
  const float* fab2 = (const float*)d_in[28];
  float* out = (float*)d_out;

  // ordered so launch #6 (ncu -s 5 -c 1) is the hv edge kernel
  k_zero<<<1024, 256>>>();                                                    // 1
  k_pre3<<<(N_V+255)/256, 256>>>(x_v, N_V, 13, 3, gvW1, hvW1, fvW1, 0);       // 2
  k_pre3<<<(N_C+255)/256, 256>>>(x_c, N_C, 14, 1, gvW1 + 13*32, nullptr, nullptr, 1); // 3
  k_pre3<<<(N_A+255)/256, 256>>>(x_a, N_A, 14, 3, hvW1 + 13*32, gaW1, faW1, 2);       // 4
  k_zero_cnt<<<(NB+255)/256, 256>>>();                                        // 5
  k_edge_hv<<<1024, 256>>>(E_A2V/16, a2v_s, a2v_t, ea_a2v, hvW1, hvb1, hvW2, hvb2);   // 6 <- profiled

  // CSR build (gv | ga)
  k_hist<<<(E_C2V+255)/256, 256>>>(c2v_t, a2v_s);
  k_s1<<<NSCAN_BLK, 1024>>>();
  k_s2<<<1, 128>>>();
  k_s3<<<NSCAN_BLK, 1024>>>();
  k_scatter<<<(E_C2V+255)/256, 256>>>(c2v_s, c2v_t, a2v_s, a2v_t, ea_c2v, ea_a2v);

  // gv: persistent-warp nodeagg (validated round 16)
  k_nodeagg_gv<<<2048, 128>>>(gvW1, gvb1, gvW2, gvb2);

  k_fv<<<(N_V+255)/256, 256>>>(fvW1, fvb1, fvW2, fvb2, gaW1);

  // ga: persistent-warp nodeagg (deg≈200 — best case)
  k_nodeagg_ga<<<1250, 128>>>(gaW1, gab1, gaW2, gab2);

  k_fa<<<(N_A+255)/256, 256>>>(faW1, fab1, faW2, fab2, out);
}